// round 1
// baseline (speedup 1.0000x reference)
#include <cuda_runtime.h>
#include <math.h>

// ---------------------------------------------------------------------------
// Problem constants: x (2,2048,512); W1 (512,2048); W2 (2048,512); HEADS=8
// M = N*S = 4096 rows. Output = concat(k, v, out), each 4096*512 fp32.
// ---------------------------------------------------------------------------
#define MROWS 4096
#define DMODEL 512
#define HID 2048
#define SEQ 2048
#define NHEADS 8
#define DHEAD 64

// Scratch (device globals: allocation-free rule)
__device__ float g_hidden[3][(size_t)MROWS * HID];   // 3 x 33.5 MB
__device__ float g_q[(size_t)MROWS * DMODEL];        // 8.4 MB

__device__ __forceinline__ float gelu_f(float x) {
    float x3 = x * x * x;
    float t = tanhf(0.7978845608028654f * (x + 0.044715f * x3));
    return 0.5f * x * (1.0f + t);
}

// ---------------------------------------------------------------------------
// GEMM: C[z] = act( A[z] @ B[z] + bias[z] ),  z = blockIdx.z in {0,1,2}
// A: M x K row-major, B: K x N row-major. 128x128x16 tile, 8x8 per thread.
// ---------------------------------------------------------------------------
__global__ void __launch_bounds__(256) gemm3_bias_act(
    const float* __restrict__ A0, const float* __restrict__ A1, const float* __restrict__ A2,
    const float* __restrict__ B0, const float* __restrict__ B1, const float* __restrict__ B2,
    const float* __restrict__ bias0, const float* __restrict__ bias1, const float* __restrict__ bias2,
    float* __restrict__ C0, float* __restrict__ C1, float* __restrict__ C2,
    int M, int N, int K, int actMask)
{
    __shared__ float As[16][132];
    __shared__ float Bs[16][132];

    const int z = blockIdx.z;
    const float* A = (z == 0) ? A0 : (z == 1) ? A1 : A2;
    const float* B = (z == 0) ? B0 : (z == 1) ? B1 : B2;
    const float* bias = (z == 0) ? bias0 : (z == 1) ? bias1 : bias2;
    float* C = (z == 0) ? C0 : (z == 1) ? C1 : C2;
    const int act = (actMask >> z) & 1;

    const int tid = threadIdx.x;
    const int bm = blockIdx.y << 7;
    const int bn = blockIdx.x << 7;
    const int tm = (tid >> 4) << 3;
    const int tn = (tid & 15) << 3;

    const int arow = tid >> 2;          // 0..63 (+64 on 2nd pass)
    const int acol = (tid & 3) << 2;    // 0,4,8,12
    const int brow = tid >> 5;          // 0..7 (+8)
    const int bcol = (tid & 31) << 2;   // 0..124

    float acc[8][8];
#pragma unroll
    for (int i = 0; i < 8; i++)
#pragma unroll
        for (int j = 0; j < 8; j++) acc[i][j] = 0.0f;

    for (int k0 = 0; k0 < K; k0 += 16) {
        __syncthreads();
#pragma unroll
        for (int t = 0; t < 2; t++) {
            int r = arow + t * 64;
            float4 v = *(const float4*)(A + (size_t)(bm + r) * K + k0 + acol);
            As[acol + 0][r] = v.x;
            As[acol + 1][r] = v.y;
            As[acol + 2][r] = v.z;
            As[acol + 3][r] = v.w;
            int rb = brow + t * 8;
            float4 w = *(const float4*)(B + (size_t)(k0 + rb) * N + bn + bcol);
            *(float4*)&Bs[rb][bcol] = w;
        }
        __syncthreads();
#pragma unroll
        for (int k = 0; k < 16; k++) {
            float ar[8], br[8];
#pragma unroll
            for (int i = 0; i < 8; i++) ar[i] = As[k][tm + i];
#pragma unroll
            for (int j = 0; j < 8; j++) br[j] = Bs[k][tn + j];
#pragma unroll
            for (int i = 0; i < 8; i++)
#pragma unroll
                for (int j = 0; j < 8; j++) acc[i][j] = fmaf(ar[i], br[j], acc[i][j]);
        }
    }

    float bv[8];
#pragma unroll
    for (int j = 0; j < 8; j++) bv[j] = bias[bn + tn + j];

#pragma unroll
    for (int i = 0; i < 8; i++) {
        float o[8];
#pragma unroll
        for (int j = 0; j < 8; j++) {
            float v = acc[i][j] + bv[j];
            o[j] = act ? gelu_f(v) : v;
        }
        float* cp = C + (size_t)(bm + tm + i) * N + bn + tn;
        *(float4*)(cp + 0) = make_float4(o[0], o[1], o[2], o[3]);
        *(float4*)(cp + 4) = make_float4(o[4], o[5], o[6], o[7]);
    }
}

// ---------------------------------------------------------------------------
// Causal flash attention, fp32. One block = (query tile of 64, batch*head).
// BM=64 queries, BK=32 keys per inner tile, Dh=64. 256 threads (16x16),
// each thread owns 4 query rows (ty+16i) and 4 output cols (tx+16j).
// ---------------------------------------------------------------------------
__global__ void __launch_bounds__(256) attention_causal(
    const float* __restrict__ Qg, const float* __restrict__ Kg,
    const float* __restrict__ Vg, float* __restrict__ Og)
{
    __shared__ float Qs[64][68];
    __shared__ float Ks[32][68];
    __shared__ float Vs[32][68];
    __shared__ float Ps[64][36];

    const int tid = threadIdx.x;
    const int tx = tid & 15;
    const int ty = tid >> 4;
    const int qt = blockIdx.x;              // query tile (64 rows)
    const int n = blockIdx.y >> 3;
    const int h = blockIdx.y & 7;

    const size_t qoff = ((size_t)(n * SEQ) + qt * 64) * DMODEL + h * DHEAD;
    const size_t koff0 = ((size_t)(n * SEQ)) * DMODEL + h * DHEAD;

    // Load Q tile (64 x 64)
#pragma unroll
    for (int p = tid; p < 1024; p += 256) {
        int r = p >> 4;
        int c = (p & 15) << 2;
        *(float4*)&Qs[r][c] = *(const float4*)(Qg + qoff + (size_t)r * DMODEL + c);
    }

    float m[4], l[4], acc[4][4];
#pragma unroll
    for (int i = 0; i < 4; i++) {
        m[i] = -1e30f;
        l[i] = 0.0f;
#pragma unroll
        for (int j = 0; j < 4; j++) acc[i][j] = 0.0f;
    }

    const int ntiles = 2 * qt + 2;  // keys 0 .. qt*64+63 inclusive
    for (int kt = 0; kt < ntiles; ++kt) {
        __syncthreads();
        // Load K,V tile (32 x 64 each)
#pragma unroll
        for (int p = tid; p < 512; p += 256) {
            int r = p >> 4;
            int c = (p & 15) << 2;
            size_t g = koff0 + (size_t)(kt * 32 + r) * DMODEL + c;
            *(float4*)&Ks[r][c] = *(const float4*)(Kg + g);
            *(float4*)&Vs[r][c] = *(const float4*)(Vg + g);
        }
        __syncthreads();

        // S = Q K^T (4 rows x 2 cols per thread)
        float s[4][2];
#pragma unroll
        for (int i = 0; i < 4; i++) { s[i][0] = 0.0f; s[i][1] = 0.0f; }
#pragma unroll
        for (int k0 = 0; k0 < 64; k0 += 4) {
            float4 kv0 = *(const float4*)&Ks[tx][k0];
            float4 kv1 = *(const float4*)&Ks[tx + 16][k0];
#pragma unroll
            for (int i = 0; i < 4; i++) {
                float4 qv = *(const float4*)&Qs[ty + 16 * i][k0];
                s[i][0] = fmaf(qv.x, kv0.x, s[i][0]);
                s[i][0] = fmaf(qv.y, kv0.y, s[i][0]);
                s[i][0] = fmaf(qv.z, kv0.z, s[i][0]);
                s[i][0] = fmaf(qv.w, kv0.w, s[i][0]);
                s[i][1] = fmaf(qv.x, kv1.x, s[i][1]);
                s[i][1] = fmaf(qv.y, kv1.y, s[i][1]);
                s[i][1] = fmaf(qv.z, kv1.z, s[i][1]);
                s[i][1] = fmaf(qv.w, kv1.w, s[i][1]);
            }
        }

        const bool maskt = (kt >= 2 * qt);
#pragma unroll
        for (int i = 0; i < 4; i++) {
            int qg = qt * 64 + ty + 16 * i;
#pragma unroll
            for (int j = 0; j < 2; j++) {
                float v = s[i][j] * 0.125f;     // 1/sqrt(64)
                if (maskt) {
                    int kg = kt * 32 + tx + 16 * j;
                    if (kg > qg) v = -1e30f;     // causal (diagonal=1)
                }
                s[i][j] = v;
            }
        }

        // Online softmax per row (16 threads share a row; replicated stats)
#pragma unroll
        for (int i = 0; i < 4; i++) {
            float mloc = fmaxf(s[i][0], s[i][1]);
#pragma unroll
            for (int o = 1; o < 16; o <<= 1)
                mloc = fmaxf(mloc, __shfl_xor_sync(0xffffffffu, mloc, o));
            float mnew = fmaxf(m[i], mloc);
            float corr = __expf(m[i] - mnew);
            float p0 = __expf(s[i][0] - mnew);
            float p1 = __expf(s[i][1] - mnew);
            float rs = p0 + p1;
#pragma unroll
            for (int o = 1; o < 16; o <<= 1)
                rs += __shfl_xor_sync(0xffffffffu, rs, o);
            l[i] = l[i] * corr + rs;
            m[i] = mnew;
#pragma unroll
            for (int j = 0; j < 4; j++) acc[i][j] *= corr;
            Ps[ty + 16 * i][tx] = p0;
            Ps[ty + 16 * i][tx + 16] = p1;
        }
        __syncthreads();

        // O += P V
#pragma unroll
        for (int kk = 0; kk < 32; kk++) {
            float p0 = Ps[ty][kk];
            float p1 = Ps[ty + 16][kk];
            float p2 = Ps[ty + 32][kk];
            float p3 = Ps[ty + 48][kk];
#pragma unroll
            for (int j = 0; j < 4; j++) {
                float vv = Vs[kk][tx + 16 * j];
                acc[0][j] = fmaf(p0, vv, acc[0][j]);
                acc[1][j] = fmaf(p1, vv, acc[1][j]);
                acc[2][j] = fmaf(p2, vv, acc[2][j]);
                acc[3][j] = fmaf(p3, vv, acc[3][j]);
            }
        }
    }

#pragma unroll
    for (int i = 0; i < 4; i++) {
        float inv = 1.0f / l[i];
#pragma unroll
        for (int j = 0; j < 4; j++) {
            Og[qoff + (size_t)(ty + 16 * i) * DMODEL + tx + 16 * j] = acc[i][j] * inv;
        }
    }
}

// ---------------------------------------------------------------------------
// Launch: q-chain, k-chain, v-chain (z-batched), then attention.
// Output layout: [k | v | out], each 4096*512 fp32.
// ---------------------------------------------------------------------------
extern "C" void kernel_launch(void* const* d_in, const int* in_sizes, int n_in,
                              void* d_out, int out_size) {
    const float* x   = (const float*)d_in[0];
    const float* qW1 = (const float*)d_in[1];
    const float* qb1 = (const float*)d_in[2];
    const float* qW2 = (const float*)d_in[3];
    const float* qb2 = (const float*)d_in[4];
    const float* kW1 = (const float*)d_in[5];
    const float* kb1 = (const float*)d_in[6];
    const float* kW2 = (const float*)d_in[7];
    const float* kb2 = (const float*)d_in[8];
    const float* vW1 = (const float*)d_in[9];
    const float* vb1 = (const float*)d_in[10];
    const float* vW2 = (const float*)d_in[11];
    const float* vb2 = (const float*)d_in[12];

    float* out = (float*)d_out;
    const size_t seg = (size_t)MROWS * DMODEL;   // 2097152
    float* k_out = out;
    float* v_out = out + seg;
    float* o_out = out + 2 * seg;

    float* gh = nullptr;
    float* gq = nullptr;
    cudaGetSymbolAddress((void**)&gh, g_hidden);
    cudaGetSymbolAddress((void**)&gq, g_q);
    float* gh0 = gh;
    float* gh1 = gh + (size_t)MROWS * HID;
    float* gh2 = gh + 2 * (size_t)MROWS * HID;

    dim3 blk(256);

    // Stage 1: hidden[z] = gelu(x @ W1[z] + b1[z])   (z = q,k,v)
    dim3 g1(HID / 128, MROWS / 128, 3);
    gemm3_bias_act<<<g1, blk>>>(x, x, x,
                                qW1, kW1, vW1,
                                qb1, kb1, vb1,
                                gh0, gh1, gh2,
                                MROWS, HID, DMODEL, 0x7);

    // Stage 2: q = h0@qW2+qb2 ; k = h1@kW2+kb2 ; v = gelu(h2@vW2+vb2)
    dim3 g2(DMODEL / 128, MROWS / 128, 3);
    gemm3_bias_act<<<g2, blk>>>(gh0, gh1, gh2,
                                qW2, kW2, vW2,
                                qb2, kb2, vb2,
                                gq, k_out, v_out,
                                MROWS, DMODEL, HID, 0x4);

    // Stage 3: attention
    dim3 ga(SEQ / 64, 2 * NHEADS);
    attention_causal<<<ga, blk>>>(gq, k_out, v_out, o_out);
}

// round 3
// speedup vs baseline: 2.0641x; 2.0641x over previous
#include <cuda_runtime.h>
#include <math.h>
#include <stdint.h>

// ---------------------------------------------------------------------------
// Problem: x (2,2048,512); W1 (512,2048); W2 (2048,512); HEADS=8
// M = 4096 rows. Output = concat(k, v, out), each 4096*512 fp32.
// GEMMs: mma.sync m16n8k8 tf32 (sm_80+ PTX — works on plain sm_100 target).
// ---------------------------------------------------------------------------
#define MROWS 4096
#define DMODEL 512
#define HID 2048
#define SEQ 2048
#define NHEADS 8
#define DHEAD 64

#define BM 128
#define BN 128
#define BKK 32
#define KSTRIDE 36   // padded smem stride (floats): conflict-free fragments

// Scratch (device globals: allocation-free rule)
__device__ __align__(16) float g_hidden[3][(size_t)MROWS * HID];
__device__ __align__(16) float g_q[(size_t)MROWS * DMODEL];
__device__ __align__(16) float g_xc[(size_t)MROWS * DMODEL];
__device__ __align__(16) float g_w1t[3][(size_t)HID * DMODEL];   // W1^T: (2048,512)
__device__ __align__(16) float g_w2t[3][(size_t)DMODEL * HID];   // W2^T: (512,2048)

// ----------------------------- helpers -------------------------------------
__device__ __forceinline__ uint32_t smem_u32(const void* p) {
    uint32_t a;
    asm("{ .reg .u64 t; cvta.to.shared.u64 t, %1; cvt.u32.u64 %0, t; }" : "=r"(a) : "l"(p));
    return a;
}
__device__ __forceinline__ void cp16(uint32_t saddr, const void* g) {
    asm volatile("cp.async.cg.shared.global [%0], [%1], 16;" :: "r"(saddr), "l"(g));
}
__device__ __forceinline__ float tf32r(float x) {
    uint32_t u;
    asm("cvt.rna.tf32.f32 %0, %1;" : "=r"(u) : "f"(x));
    return __uint_as_float(u);
}
__device__ __forceinline__ float gelu_f(float x) {
    float x3 = x * x * x;
    float t = tanhf(0.7978845608028654f * (x + 0.044715f * x3));
    return 0.5f * x * (1.0f + t);
}
__device__ __forceinline__ void mma_tf32(float* c, const uint32_t* a, const uint32_t* b) {
    asm volatile(
        "mma.sync.aligned.m16n8k8.row.col.f32.tf32.tf32.f32 "
        "{%0,%1,%2,%3}, {%4,%5,%6,%7}, {%8,%9}, {%0,%1,%2,%3};"
        : "+f"(c[0]), "+f"(c[1]), "+f"(c[2]), "+f"(c[3])
        : "r"(a[0]), "r"(a[1]), "r"(a[2]), "r"(a[3]), "r"(b[0]), "r"(b[1]));
}

// ---------------------------------------------------------------------------
// Prepass: round x to tf32
// ---------------------------------------------------------------------------
__global__ void round_x_kernel(const float* __restrict__ in, float* __restrict__ out, int n4) {
    int i = blockIdx.x * blockDim.x + threadIdx.x;
    if (i < n4) {
        float4 v = ((const float4*)in)[i];
        v.x = tf32r(v.x); v.y = tf32r(v.y); v.z = tf32r(v.z); v.w = tf32r(v.w);
        ((float4*)out)[i] = v;
    }
}

// ---------------------------------------------------------------------------
// Prepass: transpose + round weights. src R x C -> dst C x R (tf32-rounded).
// ---------------------------------------------------------------------------
__global__ void transpose_round(const float* __restrict__ s0, const float* __restrict__ s1,
                                const float* __restrict__ s2,
                                float* __restrict__ d0, float* __restrict__ d1,
                                float* __restrict__ d2, int R, int C) {
    __shared__ float tile[32][33];
    const int z = blockIdx.z;
    const float* src = (z == 0) ? s0 : (z == 1) ? s1 : s2;
    float* dst = (z == 0) ? d0 : (z == 1) ? d1 : d2;
    int tx = threadIdx.x, ty = threadIdx.y;
    int bx = blockIdx.x, by = blockIdx.y;
#pragma unroll
    for (int j = 0; j < 4; j++) {
        int r = by * 32 + ty + j * 8;
        int c = bx * 32 + tx;
        tile[ty + j * 8][tx] = tf32r(src[(size_t)r * C + c]);
    }
    __syncthreads();
#pragma unroll
    for (int j = 0; j < 4; j++) {
        int dr = bx * 32 + ty + j * 8;
        int dc = by * 32 + tx;
        dst[(size_t)dr * R + dc] = tile[tx][ty + j * 8];
    }
}

// ---------------------------------------------------------------------------
// Tensor-core tf32 GEMM: C[z] = act(A[z] @ Bt[z]^T + bias[z])
// A: M x K row-major (tf32-rounded), Bt: N x K row-major (W^T, rounded).
// 128x128x32 CTA tile, 8 warps (2 M x 4 N), warp tile 64x32.
// mode per z (2 bits): 0=none, 1=gelu, 2=gelu+round-to-tf32
// Smem: As/Bs double buffered, row stride 36 floats.
// ---------------------------------------------------------------------------
#define AS_OFF(buf) ((buf) * 4608u)
#define BS_OFF(buf) (9216u + (buf) * 4608u)
#define SM_BYTES (18432 * 4)

__global__ void __launch_bounds__(256, 2) gemm_mma(
    const float* __restrict__ A0, const float* __restrict__ A1, const float* __restrict__ A2,
    const float* __restrict__ B0, const float* __restrict__ B1, const float* __restrict__ B2,
    const float* __restrict__ bias0, const float* __restrict__ bias1, const float* __restrict__ bias2,
    float* __restrict__ C0, float* __restrict__ C1, float* __restrict__ C2,
    int N, int K, int actModes)
{
    extern __shared__ float smem[];
    const uint32_t sb = smem_u32(smem);

    const int z = blockIdx.z;
    const float* A = (z == 0) ? A0 : (z == 1) ? A1 : A2;
    const float* B = (z == 0) ? B0 : (z == 1) ? B1 : B2;
    const float* bias = (z == 0) ? bias0 : (z == 1) ? bias1 : bias2;
    float* C = (z == 0) ? C0 : (z == 1) ? C1 : C2;
    const int mode = (actModes >> (2 * z)) & 3;

    const int tid = threadIdx.x;
    const int wid = tid >> 5;
    const int lane = tid & 31;
    const int bm = blockIdx.y * BM;
    const int bn = blockIdx.x * BN;
    const int wm = (wid >> 2) * 64;      // warp row offset within tile
    const int wn = (wid & 3) * 32;       // warp col offset within tile

    const int lr = lane >> 2;            // 0..7
    const int lc = lane & 3;             // 0..3

    // Global load indexing: 1024 16B-chunks per operand tile, 4 per thread.
    const int grow = tid >> 3;           // +64 per j for 2 rounds? no: 256 threads*4
    const int gc16 = tid & 7;

    float acc[4][4][4];
#pragma unroll
    for (int i = 0; i < 4; i++)
#pragma unroll
        for (int j = 0; j < 4; j++)
#pragma unroll
            for (int t = 0; t < 4; t++) acc[i][j][t] = 0.0f;

    auto loadTile = [&](int kc, int buf) {
        const float* ga = A + (size_t)(bm + grow) * K + kc * BKK + gc16 * 4;
        const float* gb = B + (size_t)(bn + grow) * K + kc * BKK + gc16 * 4;
        uint32_t sa = sb + AS_OFF(buf) * 4 + grow * (KSTRIDE * 4) + gc16 * 16;
        uint32_t sbb = sb + BS_OFF(buf) * 4 + grow * (KSTRIDE * 4) + gc16 * 16;
#pragma unroll
        for (int j = 0; j < 4; j++) {
            cp16(sa + j * 32 * (KSTRIDE * 4), ga + (size_t)(32 * j) * K);
            cp16(sbb + j * 32 * (KSTRIDE * 4), gb + (size_t)(32 * j) * K);
        }
        asm volatile("cp.async.commit_group;" ::: "memory");
    };

    const int NC = K / BKK;
    loadTile(0, 0);

    for (int c = 0; c < NC; c++) {
        const int b = c & 1;
        __syncthreads();   // prev compute done: safe to overwrite b^1
        if (c + 1 < NC) {
            loadTile(c + 1, b ^ 1);
            asm volatile("cp.async.wait_group 1;" ::: "memory");
        } else {
            asm volatile("cp.async.wait_group 0;" ::: "memory");
        }
        __syncthreads();

        const float* As = smem + AS_OFF(b);
        const float* Bs = smem + BS_OFF(b);
#pragma unroll
        for (int ks = 0; ks < 4; ks++) {
            const int k0 = ks * 8;
            uint32_t af[4][4], bf[4][2];
#pragma unroll
            for (int mt = 0; mt < 4; mt++) {
                int r = wm + mt * 16 + lr;
                const float* p = As + r * KSTRIDE + k0 + lc;
                af[mt][0] = __float_as_uint(p[0]);
                af[mt][1] = __float_as_uint(p[8 * KSTRIDE]);
                af[mt][2] = __float_as_uint(p[4]);
                af[mt][3] = __float_as_uint(p[8 * KSTRIDE + 4]);
            }
#pragma unroll
            for (int nt = 0; nt < 4; nt++) {
                int n = wn + nt * 8 + lr;
                const float* p = Bs + n * KSTRIDE + k0 + lc;
                bf[nt][0] = __float_as_uint(p[0]);
                bf[nt][1] = __float_as_uint(p[4]);
            }
#pragma unroll
            for (int mt = 0; mt < 4; mt++)
#pragma unroll
                for (int nt = 0; nt < 4; nt++)
                    mma_tf32(acc[mt][nt], af[mt], bf[nt]);
        }
    }

    // Epilogue: bias + act (+ tf32 round), direct float2 stores.
    float2 bv[4];
#pragma unroll
    for (int nt = 0; nt < 4; nt++) {
        int col = bn + wn + nt * 8 + 2 * lc;
        bv[nt] = *(const float2*)(bias + col);
    }
#pragma unroll
    for (int mt = 0; mt < 4; mt++) {
        int row0 = bm + wm + mt * 16 + lr;
#pragma unroll
        for (int nt = 0; nt < 4; nt++) {
            int col = bn + wn + nt * 8 + 2 * lc;
#pragma unroll
            for (int half = 0; half < 2; half++) {
                int row = row0 + half * 8;
                float v0 = acc[mt][nt][2 * half + 0] + bv[nt].x;
                float v1 = acc[mt][nt][2 * half + 1] + bv[nt].y;
                if (mode >= 1) { v0 = gelu_f(v0); v1 = gelu_f(v1); }
                if (mode == 2) { v0 = tf32r(v0); v1 = tf32r(v1); }
                *(float2*)(C + (size_t)row * N + col) = make_float2(v0, v1);
            }
        }
    }
}

// ---------------------------------------------------------------------------
// Causal flash attention, fp32 (unchanged from R1).
// ---------------------------------------------------------------------------
__global__ void __launch_bounds__(256) attention_causal(
    const float* __restrict__ Qg, const float* __restrict__ Kg,
    const float* __restrict__ Vg, float* __restrict__ Og)
{
    __shared__ float Qs[64][68];
    __shared__ float Ks[32][68];
    __shared__ float Vs[32][68];
    __shared__ float Ps[64][36];

    const int tid = threadIdx.x;
    const int tx = tid & 15;
    const int ty = tid >> 4;
    const int qt = blockIdx.x;
    const int n = blockIdx.y >> 3;
    const int h = blockIdx.y & 7;

    const size_t qoff = ((size_t)(n * SEQ) + qt * 64) * DMODEL + h * DHEAD;
    const size_t koff0 = ((size_t)(n * SEQ)) * DMODEL + h * DHEAD;

#pragma unroll
    for (int p = tid; p < 1024; p += 256) {
        int r = p >> 4;
        int c = (p & 15) << 2;
        *(float4*)&Qs[r][c] = *(const float4*)(Qg + qoff + (size_t)r * DMODEL + c);
    }

    float m[4], l[4], acc[4][4];
#pragma unroll
    for (int i = 0; i < 4; i++) {
        m[i] = -1e30f;
        l[i] = 0.0f;
#pragma unroll
        for (int j = 0; j < 4; j++) acc[i][j] = 0.0f;
    }

    const int ntiles = 2 * qt + 2;
    for (int kt = 0; kt < ntiles; ++kt) {
        __syncthreads();
#pragma unroll
        for (int p = tid; p < 512; p += 256) {
            int r = p >> 4;
            int c = (p & 15) << 2;
            size_t g = koff0 + (size_t)(kt * 32 + r) * DMODEL + c;
            *(float4*)&Ks[r][c] = *(const float4*)(Kg + g);
            *(float4*)&Vs[r][c] = *(const float4*)(Vg + g);
        }
        __syncthreads();

        float s[4][2];
#pragma unroll
        for (int i = 0; i < 4; i++) { s[i][0] = 0.0f; s[i][1] = 0.0f; }
#pragma unroll
        for (int k0 = 0; k0 < 64; k0 += 4) {
            float4 kv0 = *(const float4*)&Ks[tx][k0];
            float4 kv1 = *(const float4*)&Ks[tx + 16][k0];
#pragma unroll
            for (int i = 0; i < 4; i++) {
                float4 qv = *(const float4*)&Qs[ty + 16 * i][k0];
                s[i][0] = fmaf(qv.x, kv0.x, s[i][0]);
                s[i][0] = fmaf(qv.y, kv0.y, s[i][0]);
                s[i][0] = fmaf(qv.z, kv0.z, s[i][0]);
                s[i][0] = fmaf(qv.w, kv0.w, s[i][0]);
                s[i][1] = fmaf(qv.x, kv1.x, s[i][1]);
                s[i][1] = fmaf(qv.y, kv1.y, s[i][1]);
                s[i][1] = fmaf(qv.z, kv1.z, s[i][1]);
                s[i][1] = fmaf(qv.w, kv1.w, s[i][1]);
            }
        }

        const bool maskt = (kt >= 2 * qt);
#pragma unroll
        for (int i = 0; i < 4; i++) {
            int qg = qt * 64 + ty + 16 * i;
#pragma unroll
            for (int j = 0; j < 2; j++) {
                float v = s[i][j] * 0.125f;
                if (maskt) {
                    int kg = kt * 32 + tx + 16 * j;
                    if (kg > qg) v = -1e30f;
                }
                s[i][j] = v;
            }
        }

#pragma unroll
        for (int i = 0; i < 4; i++) {
            float mloc = fmaxf(s[i][0], s[i][1]);
#pragma unroll
            for (int o = 1; o < 16; o <<= 1)
                mloc = fmaxf(mloc, __shfl_xor_sync(0xffffffffu, mloc, o));
            float mnew = fmaxf(m[i], mloc);
            float corr = __expf(m[i] - mnew);
            float p0 = __expf(s[i][0] - mnew);
            float p1 = __expf(s[i][1] - mnew);
            float rs = p0 + p1;
#pragma unroll
            for (int o = 1; o < 16; o <<= 1)
                rs += __shfl_xor_sync(0xffffffffu, rs, o);
            l[i] = l[i] * corr + rs;
            m[i] = mnew;
#pragma unroll
            for (int j = 0; j < 4; j++) acc[i][j] *= corr;
            Ps[ty + 16 * i][tx] = p0;
            Ps[ty + 16 * i][tx + 16] = p1;
        }
        __syncthreads();

#pragma unroll
        for (int kk = 0; kk < 32; kk++) {
            float p0 = Ps[ty][kk];
            float p1 = Ps[ty + 16][kk];
            float p2 = Ps[ty + 32][kk];
            float p3 = Ps[ty + 48][kk];
#pragma unroll
            for (int j = 0; j < 4; j++) {
                float vv = Vs[kk][tx + 16 * j];
                acc[0][j] = fmaf(p0, vv, acc[0][j]);
                acc[1][j] = fmaf(p1, vv, acc[1][j]);
                acc[2][j] = fmaf(p2, vv, acc[2][j]);
                acc[3][j] = fmaf(p3, vv, acc[3][j]);
            }
        }
    }

#pragma unroll
    for (int i = 0; i < 4; i++) {
        float inv = 1.0f / l[i];
#pragma unroll
        for (int j = 0; j < 4; j++) {
            Og[qoff + (size_t)(ty + 16 * i) * DMODEL + tx + 16 * j] = acc[i][j] * inv;
        }
    }
}

// ---------------------------------------------------------------------------
extern "C" void kernel_launch(void* const* d_in, const int* in_sizes, int n_in,
                              void* d_out, int out_size) {
    const float* x   = (const float*)d_in[0];
    const float* qW1 = (const float*)d_in[1];
    const float* qb1 = (const float*)d_in[2];
    const float* qW2 = (const float*)d_in[3];
    const float* qb2 = (const float*)d_in[4];
    const float* kW1 = (const float*)d_in[5];
    const float* kb1 = (const float*)d_in[6];
    const float* kW2 = (const float*)d_in[7];
    const float* kb2 = (const float*)d_in[8];
    const float* vW1 = (const float*)d_in[9];
    const float* vb1 = (const float*)d_in[10];
    const float* vW2 = (const float*)d_in[11];
    const float* vb2 = (const float*)d_in[12];

    float* out = (float*)d_out;
    const size_t seg = (size_t)MROWS * DMODEL;
    float* k_out = out;
    float* v_out = out + seg;
    float* o_out = out + 2 * seg;

    float* gh = nullptr; float* gq = nullptr; float* gxc = nullptr;
    float* gw1t = nullptr; float* gw2t = nullptr;
    cudaGetSymbolAddress((void**)&gh, g_hidden);
    cudaGetSymbolAddress((void**)&gq, g_q);
    cudaGetSymbolAddress((void**)&gxc, g_xc);
    cudaGetSymbolAddress((void**)&gw1t, g_w1t);
    cudaGetSymbolAddress((void**)&gw2t, g_w2t);
    float* gh0 = gh;
    float* gh1 = gh + (size_t)MROWS * HID;
    float* gh2 = gh + 2 * (size_t)MROWS * HID;
    float* w1t0 = gw1t;
    float* w1t1 = gw1t + (size_t)HID * DMODEL;
    float* w1t2 = gw1t + 2 * (size_t)HID * DMODEL;
    float* w2t0 = gw2t;
    float* w2t1 = gw2t + (size_t)DMODEL * HID;
    float* w2t2 = gw2t + 2 * (size_t)DMODEL * HID;

    cudaFuncSetAttribute(gemm_mma, cudaFuncAttributeMaxDynamicSharedMemorySize, SM_BYTES);

    // Prepass: round x; transpose+round weights
    {
        int n4 = (MROWS * DMODEL) / 4;
        round_x_kernel<<<(n4 + 255) / 256, 256>>>(x, gxc, n4);
        dim3 tb(32, 8);
        transpose_round<<<dim3(HID / 32, DMODEL / 32, 3), tb>>>(qW1, kW1, vW1, w1t0, w1t1, w1t2, DMODEL, HID);
        transpose_round<<<dim3(DMODEL / 32, HID / 32, 3), tb>>>(qW2, kW2, vW2, w2t0, w2t1, w2t2, HID, DMODEL);
    }

    // Stage 1: hidden[z] = tf32round(gelu(x @ W1[z] + b1[z]))
    {
        dim3 g(HID / BN, MROWS / BM, 3);
        gemm_mma<<<g, 256, SM_BYTES>>>(gxc, gxc, gxc,
                                       w1t0, w1t1, w1t2,
                                       qb1, kb1, vb1,
                                       gh0, gh1, gh2,
                                       HID, DMODEL, (2) | (2 << 2) | (2 << 4));
    }
    // Stage 2: q = h0@qW2+qb2 ; k = h1@kW2+kb2 ; v = gelu(h2@vW2+vb2)
    {
        dim3 g(DMODEL / BN, MROWS / BM, 3);
        gemm_mma<<<g, 256, SM_BYTES>>>(gh0, gh1, gh2,
                                       w2t0, w2t1, w2t2,
                                       qb2, kb2, vb2,
                                       gq, k_out, v_out,
                                       DMODEL, HID, (0) | (0 << 2) | (1 << 4));
    }
    // Stage 3: attention
    {
        dim3 ga(SEQ / 64, 2 * NHEADS);
        attention_causal<<<ga, 256>>>(gq, k_out, v_out, o_out);
    }
}

// round 5
// speedup vs baseline: 2.9298x; 1.4194x over previous
#include <cuda_runtime.h>
#include <math.h>
#include <stdint.h>

// ---------------------------------------------------------------------------
// Problem: x (2,2048,512); W1 (512,2048); W2 (2048,512); HEADS=8
// M = 4096 rows. Output = concat(k, v, out), each 4096*512 fp32.
// GEMMs + attention on mma.sync m16n8k8 tf32 (plain sm_100 target).
// ---------------------------------------------------------------------------
#define MROWS 4096
#define DMODEL 512
#define HID 2048
#define SEQ 2048
#define NHEADS 8
#define DHEAD 64

#define BM 128
#define BN 128
#define BKK 32
#define KSTRIDE 36   // padded smem stride (floats): conflict-free fragments

// Scratch (device globals: allocation-free rule)
__device__ __align__(16) float g_hidden[3][(size_t)MROWS * HID];
__device__ __align__(16) float g_q[(size_t)MROWS * DMODEL];
__device__ __align__(16) float g_xc[(size_t)MROWS * DMODEL];
__device__ __align__(16) float g_w1t[3][(size_t)HID * DMODEL];   // W1^T: (2048,512)
__device__ __align__(16) float g_w2t[3][(size_t)DMODEL * HID];   // W2^T: (512,2048)

// ----------------------------- helpers -------------------------------------
__device__ __forceinline__ uint32_t smem_u32(const void* p) {
    uint32_t a;
    asm("{ .reg .u64 t; cvta.to.shared.u64 t, %1; cvt.u32.u64 %0, t; }" : "=r"(a) : "l"(p));
    return a;
}
__device__ __forceinline__ void cp16(uint32_t saddr, const void* g) {
    asm volatile("cp.async.cg.shared.global [%0], [%1], 16;" :: "r"(saddr), "l"(g));
}
__device__ __forceinline__ float tf32r(float x) {
    uint32_t u;
    asm("cvt.rna.tf32.f32 %0, %1;" : "=r"(u) : "f"(x));
    return __uint_as_float(u);
}
__device__ __forceinline__ float gelu_f(float x) {
    float x3 = x * x * x;
    float t = tanhf(0.7978845608028654f * (x + 0.044715f * x3));
    return 0.5f * x * (1.0f + t);
}
__device__ __forceinline__ void mma_tf32(float* c, const uint32_t* a, const uint32_t* b) {
    asm volatile(
        "mma.sync.aligned.m16n8k8.row.col.f32.tf32.tf32.f32 "
        "{%0,%1,%2,%3}, {%4,%5,%6,%7}, {%8,%9}, {%0,%1,%2,%3};"
        : "+f"(c[0]), "+f"(c[1]), "+f"(c[2]), "+f"(c[3])
        : "r"(a[0]), "r"(a[1]), "r"(a[2]), "r"(a[3]), "r"(b[0]), "r"(b[1]));
}

// ---------------------------------------------------------------------------
// Prepass: round x to tf32
// ---------------------------------------------------------------------------
__global__ void round_x_kernel(const float* __restrict__ in, float* __restrict__ out, int n4) {
    int i = blockIdx.x * blockDim.x + threadIdx.x;
    if (i < n4) {
        float4 v = ((const float4*)in)[i];
        v.x = tf32r(v.x); v.y = tf32r(v.y); v.z = tf32r(v.z); v.w = tf32r(v.w);
        ((float4*)out)[i] = v;
    }
}

// ---------------------------------------------------------------------------
// Prepass: transpose + round weights. src R x C -> dst C x R (tf32-rounded).
// ---------------------------------------------------------------------------
__global__ void transpose_round(const float* __restrict__ s0, const float* __restrict__ s1,
                                const float* __restrict__ s2,
                                float* __restrict__ d0, float* __restrict__ d1,
                                float* __restrict__ d2, int R, int C) {
    __shared__ float tile[32][33];
    const int z = blockIdx.z;
    const float* src = (z == 0) ? s0 : (z == 1) ? s1 : s2;
    float* dst = (z == 0) ? d0 : (z == 1) ? d1 : d2;
    int tx = threadIdx.x, ty = threadIdx.y;
    int bx = blockIdx.x, by = blockIdx.y;
#pragma unroll
    for (int j = 0; j < 4; j++) {
        int r = by * 32 + ty + j * 8;
        int c = bx * 32 + tx;
        tile[ty + j * 8][tx] = tf32r(src[(size_t)r * C + c]);
    }
    __syncthreads();
#pragma unroll
    for (int j = 0; j < 4; j++) {
        int dr = bx * 32 + ty + j * 8;
        int dc = by * 32 + tx;
        dst[(size_t)dr * R + dc] = tile[tx][ty + j * 8];
    }
}

// ---------------------------------------------------------------------------
// Tensor-core tf32 GEMM (unchanged from R3): C[z] = act(A[z] @ Bt[z]^T + b[z])
// ---------------------------------------------------------------------------
#define AS_OFF(buf) ((buf) * 4608u)
#define BS_OFF(buf) (9216u + (buf) * 4608u)
#define SM_BYTES (18432 * 4)

__global__ void __launch_bounds__(256, 2) gemm_mma(
    const float* __restrict__ A0, const float* __restrict__ A1, const float* __restrict__ A2,
    const float* __restrict__ B0, const float* __restrict__ B1, const float* __restrict__ B2,
    const float* __restrict__ bias0, const float* __restrict__ bias1, const float* __restrict__ bias2,
    float* __restrict__ C0, float* __restrict__ C1, float* __restrict__ C2,
    int N, int K, int actModes)
{
    extern __shared__ float smem[];
    const uint32_t sb = smem_u32(smem);

    const int z = blockIdx.z;
    const float* A = (z == 0) ? A0 : (z == 1) ? A1 : A2;
    const float* B = (z == 0) ? B0 : (z == 1) ? B1 : B2;
    const float* bias = (z == 0) ? bias0 : (z == 1) ? bias1 : bias2;
    float* C = (z == 0) ? C0 : (z == 1) ? C1 : C2;
    const int mode = (actModes >> (2 * z)) & 3;

    const int tid = threadIdx.x;
    const int wid = tid >> 5;
    const int lane = tid & 31;
    const int bm = blockIdx.y * BM;
    const int bn = blockIdx.x * BN;
    const int wm = (wid >> 2) * 64;
    const int wn = (wid & 3) * 32;

    const int lr = lane >> 2;
    const int lc = lane & 3;

    const int grow = tid >> 3;
    const int gc16 = tid & 7;

    float acc[4][4][4];
#pragma unroll
    for (int i = 0; i < 4; i++)
#pragma unroll
        for (int j = 0; j < 4; j++)
#pragma unroll
            for (int t = 0; t < 4; t++) acc[i][j][t] = 0.0f;

    auto loadTile = [&](int kc, int buf) {
        const float* ga = A + (size_t)(bm + grow) * K + kc * BKK + gc16 * 4;
        const float* gb = B + (size_t)(bn + grow) * K + kc * BKK + gc16 * 4;
        uint32_t sa = sb + AS_OFF(buf) * 4 + grow * (KSTRIDE * 4) + gc16 * 16;
        uint32_t sbb = sb + BS_OFF(buf) * 4 + grow * (KSTRIDE * 4) + gc16 * 16;
#pragma unroll
        for (int j = 0; j < 4; j++) {
            cp16(sa + j * 32 * (KSTRIDE * 4), ga + (size_t)(32 * j) * K);
            cp16(sbb + j * 32 * (KSTRIDE * 4), gb + (size_t)(32 * j) * K);
        }
        asm volatile("cp.async.commit_group;" ::: "memory");
    };

    const int NC = K / BKK;
    loadTile(0, 0);

    for (int c = 0; c < NC; c++) {
        const int b = c & 1;
        __syncthreads();
        if (c + 1 < NC) {
            loadTile(c + 1, b ^ 1);
            asm volatile("cp.async.wait_group 1;" ::: "memory");
        } else {
            asm volatile("cp.async.wait_group 0;" ::: "memory");
        }
        __syncthreads();

        const float* As = smem + AS_OFF(b);
        const float* Bs = smem + BS_OFF(b);
#pragma unroll
        for (int ks = 0; ks < 4; ks++) {
            const int k0 = ks * 8;
            uint32_t af[4][4], bf[4][2];
#pragma unroll
            for (int mt = 0; mt < 4; mt++) {
                int r = wm + mt * 16 + lr;
                const float* p = As + r * KSTRIDE + k0 + lc;
                af[mt][0] = __float_as_uint(p[0]);
                af[mt][1] = __float_as_uint(p[8 * KSTRIDE]);
                af[mt][2] = __float_as_uint(p[4]);
                af[mt][3] = __float_as_uint(p[8 * KSTRIDE + 4]);
            }
#pragma unroll
            for (int nt = 0; nt < 4; nt++) {
                int n = wn + nt * 8 + lr;
                const float* p = Bs + n * KSTRIDE + k0 + lc;
                bf[nt][0] = __float_as_uint(p[0]);
                bf[nt][1] = __float_as_uint(p[4]);
            }
#pragma unroll
            for (int mt = 0; mt < 4; mt++)
#pragma unroll
                for (int nt = 0; nt < 4; nt++)
                    mma_tf32(acc[mt][nt], af[mt], bf[nt]);
        }
    }

    float2 bv[4];
#pragma unroll
    for (int nt = 0; nt < 4; nt++) {
        int col = bn + wn + nt * 8 + 2 * lc;
        bv[nt] = *(const float2*)(bias + col);
    }
#pragma unroll
    for (int mt = 0; mt < 4; mt++) {
        int row0 = bm + wm + mt * 16 + lr;
#pragma unroll
        for (int nt = 0; nt < 4; nt++) {
            int col = bn + wn + nt * 8 + 2 * lc;
#pragma unroll
            for (int half = 0; half < 2; half++) {
                int row = row0 + half * 8;
                float v0 = acc[mt][nt][2 * half + 0] + bv[nt].x;
                float v1 = acc[mt][nt][2 * half + 1] + bv[nt].y;
                if (mode >= 1) { v0 = gelu_f(v0); v1 = gelu_f(v1); }
                if (mode == 2) { v0 = tf32r(v0); v1 = tf32r(v1); }
                *(float2*)(C + (size_t)row * N + col) = make_float2(v0, v1);
            }
        }
    }
}

// ---------------------------------------------------------------------------
// Tensor-core causal flash attention (tf32 mma).
// CTA: 128 query rows of one (batch,head); 8 warps x 16 rows.
// Per 64-key tile: S = Q K^T (mma), fragment-layout online softmax,
// P staged in warp-private smem rows, O += P V (mma).
// Smem (floats): Ps[128*68] | Ks[64*68] | Vt[64*68]
// ---------------------------------------------------------------------------
#define ATT_PS 0
#define ATT_KS 8704
#define ATT_VT 13056
#define ATT_SMEM_BYTES (17408 * 4)

__global__ void __launch_bounds__(256) attention_mma(
    const float* __restrict__ Qg, const float* __restrict__ Kg,
    const float* __restrict__ Vg, float* __restrict__ Og)
{
    extern __shared__ float sm[];
    float* Ps = sm + ATT_PS;
    float* Ks = sm + ATT_KS;
    float* Vt = sm + ATT_VT;

    const int tid = threadIdx.x;
    const int wid = tid >> 5;
    const int lane = tid & 31;
    const int lr = lane >> 2;
    const int lc = lane & 3;
    const int qt = gridDim.x - 1 - blockIdx.x;   // heavy tiles first
    const int nb = blockIdx.y >> 3;
    const int h  = blockIdx.y & 7;
    const int bm = qt * 128;
    const int wm = wid * 16;

    const size_t base = ((size_t)nb * SEQ) * DMODEL + (size_t)h * DHEAD;

    // Stage Q (tf32-rounded) into Ps area, then load per-warp fragments.
#pragma unroll
    for (int j = 0; j < 8; j++) {
        int idx = tid + 256 * j;
        int r = idx >> 4;            // 0..127
        int c = (idx & 15) * 4;
        float4 v = *(const float4*)(Qg + base + (size_t)(bm + r) * DMODEL + c);
        float* p = Ps + r * 68 + c;
        p[0] = tf32r(v.x); p[1] = tf32r(v.y); p[2] = tf32r(v.z); p[3] = tf32r(v.w);
    }
    __syncthreads();

    uint32_t qf[8][4];
#pragma unroll
    for (int ks = 0; ks < 8; ks++) {
        const float* p = Ps + (wm + lr) * 68 + ks * 8 + lc;
        qf[ks][0] = __float_as_uint(p[0]);
        qf[ks][1] = __float_as_uint(p[8 * 68]);
        qf[ks][2] = __float_as_uint(p[4]);
        qf[ks][3] = __float_as_uint(p[8 * 68 + 4]);
    }

    float of[8][4];
#pragma unroll
    for (int nf = 0; nf < 8; nf++)
#pragma unroll
        for (int t = 0; t < 4; t++) of[nf][t] = 0.0f;
    float m0 = -1e30f, m1 = -1e30f, l0 = 0.0f, l1 = 0.0f;

    const int r0g = bm + wm + lr;
    const int r1g = r0g + 8;
    const int ntiles = qt * 2 + 2;

    for (int kt = 0; kt < ntiles; kt++) {
        __syncthreads();   // prev tile's mma reads of Ks/Vt done
        // Load K tile and transposed V tile (64 keys x 64 dims), rounded.
#pragma unroll
        for (int j = 0; j < 4; j++) {
            int idx = tid + 256 * j;
            int r = idx >> 4;            // key 0..63
            int c = (idx & 15) * 4;
            size_t g = base + (size_t)(kt * 64 + r) * DMODEL + c;
            float4 kv = *(const float4*)(Kg + g);
            float* pk = Ks + r * 68 + c;
            pk[0] = tf32r(kv.x); pk[1] = tf32r(kv.y); pk[2] = tf32r(kv.z); pk[3] = tf32r(kv.w);
            float4 vv = *(const float4*)(Vg + g);
            Vt[(c + 0) * 68 + r] = tf32r(vv.x);
            Vt[(c + 1) * 68 + r] = tf32r(vv.y);
            Vt[(c + 2) * 68 + r] = tf32r(vv.z);
            Vt[(c + 3) * 68 + r] = tf32r(vv.w);
        }
        __syncthreads();

        // S = Q K^T  (warp rows x 64 keys)
        float sf[8][4];
#pragma unroll
        for (int nf = 0; nf < 8; nf++)
#pragma unroll
            for (int t = 0; t < 4; t++) sf[nf][t] = 0.0f;
#pragma unroll
        for (int ks = 0; ks < 8; ks++) {
            uint32_t bf[8][2];
#pragma unroll
            for (int nf = 0; nf < 8; nf++) {
                const float* p = Ks + (nf * 8 + lr) * 68 + ks * 8 + lc;
                bf[nf][0] = __float_as_uint(p[0]);
                bf[nf][1] = __float_as_uint(p[4]);
            }
#pragma unroll
            for (int nf = 0; nf < 8; nf++)
                mma_tf32(sf[nf], qf[ks], bf[nf]);
        }

        // Scale + causal mask (only last two tiles touch the diagonal)
        const bool diag = (kt >= ntiles - 2);
#pragma unroll
        for (int nf = 0; nf < 8; nf++) {
            int c0 = kt * 64 + nf * 8 + 2 * lc;
            sf[nf][0] *= 0.125f; sf[nf][1] *= 0.125f;
            sf[nf][2] *= 0.125f; sf[nf][3] *= 0.125f;
            if (diag) {
                if (c0     > r0g) sf[nf][0] = -1e30f;
                if (c0 + 1 > r0g) sf[nf][1] = -1e30f;
                if (c0     > r1g) sf[nf][2] = -1e30f;
                if (c0 + 1 > r1g) sf[nf][3] = -1e30f;
            }
        }

        // Online softmax; row stats live in a 4-lane quad.
        float mx0 = -1e30f, mx1 = -1e30f;
#pragma unroll
        for (int nf = 0; nf < 8; nf++) {
            mx0 = fmaxf(mx0, fmaxf(sf[nf][0], sf[nf][1]));
            mx1 = fmaxf(mx1, fmaxf(sf[nf][2], sf[nf][3]));
        }
        mx0 = fmaxf(mx0, __shfl_xor_sync(0xffffffffu, mx0, 1));
        mx0 = fmaxf(mx0, __shfl_xor_sync(0xffffffffu, mx0, 2));
        mx1 = fmaxf(mx1, __shfl_xor_sync(0xffffffffu, mx1, 1));
        mx1 = fmaxf(mx1, __shfl_xor_sync(0xffffffffu, mx1, 2));
        float mn0 = fmaxf(m0, mx0), mn1 = fmaxf(m1, mx1);
        float corr0 = __expf(m0 - mn0), corr1 = __expf(m1 - mn1);

        float rs0 = 0.0f, rs1 = 0.0f;
        float* pr0 = Ps + (wm + lr) * 68;
        float* pr1 = Ps + (wm + lr + 8) * 68;
#pragma unroll
        for (int nf = 0; nf < 8; nf++) {
            float p0 = __expf(sf[nf][0] - mn0);
            float p1 = __expf(sf[nf][1] - mn0);
            float p2 = __expf(sf[nf][2] - mn1);
            float p3 = __expf(sf[nf][3] - mn1);
            rs0 += p0 + p1;
            rs1 += p2 + p3;
            *(float2*)(pr0 + nf * 8 + 2 * lc) = make_float2(tf32r(p0), tf32r(p1));
            *(float2*)(pr1 + nf * 8 + 2 * lc) = make_float2(tf32r(p2), tf32r(p3));
        }
        rs0 += __shfl_xor_sync(0xffffffffu, rs0, 1);
        rs0 += __shfl_xor_sync(0xffffffffu, rs0, 2);
        rs1 += __shfl_xor_sync(0xffffffffu, rs1, 1);
        rs1 += __shfl_xor_sync(0xffffffffu, rs1, 2);
        l0 = l0 * corr0 + rs0;
        l1 = l1 * corr1 + rs1;
        m0 = mn0; m1 = mn1;
#pragma unroll
        for (int nf = 0; nf < 8; nf++) {
            of[nf][0] *= corr0; of[nf][1] *= corr0;
            of[nf][2] *= corr1; of[nf][3] *= corr1;
        }
        __syncwarp();   // P rows are warp-private: warp sync suffices

        // O += P V
#pragma unroll
        for (int ks = 0; ks < 8; ks++) {
            uint32_t af[4];
            const float* p = Ps + (wm + lr) * 68 + ks * 8 + lc;
            af[0] = __float_as_uint(p[0]);
            af[1] = __float_as_uint(p[8 * 68]);
            af[2] = __float_as_uint(p[4]);
            af[3] = __float_as_uint(p[8 * 68 + 4]);
#pragma unroll
            for (int nf = 0; nf < 8; nf++) {
                uint32_t bf2[2];
                const float* pv = Vt + (nf * 8 + lr) * 68 + ks * 8 + lc;
                bf2[0] = __float_as_uint(pv[0]);
                bf2[1] = __float_as_uint(pv[4]);
                mma_tf32(of[nf], af, bf2);
            }
        }
    }

    const float inv0 = 1.0f / l0;
    const float inv1 = 1.0f / l1;
#pragma unroll
    for (int nf = 0; nf < 8; nf++) {
        int col = nf * 8 + 2 * lc;
        *(float2*)(Og + base + (size_t)r0g * DMODEL + col) =
            make_float2(of[nf][0] * inv0, of[nf][1] * inv0);
        *(float2*)(Og + base + (size_t)r1g * DMODEL + col) =
            make_float2(of[nf][2] * inv1, of[nf][3] * inv1);
    }
}

// ---------------------------------------------------------------------------
extern "C" void kernel_launch(void* const* d_in, const int* in_sizes, int n_in,
                              void* d_out, int out_size) {
    const float* x   = (const float*)d_in[0];
    const float* qW1 = (const float*)d_in[1];
    const float* qb1 = (const float*)d_in[2];
    const float* qW2 = (const float*)d_in[3];
    const float* qb2 = (const float*)d_in[4];
    const float* kW1 = (const float*)d_in[5];
    const float* kb1 = (const float*)d_in[6];
    const float* kW2 = (const float*)d_in[7];
    const float* kb2 = (const float*)d_in[8];
    const float* vW1 = (const float*)d_in[9];
    const float* vb1 = (const float*)d_in[10];
    const float* vW2 = (const float*)d_in[11];
    const float* vb2 = (const float*)d_in[12];

    float* out = (float*)d_out;
    const size_t seg = (size_t)MROWS * DMODEL;
    float* k_out = out;
    float* v_out = out + seg;
    float* o_out = out + 2 * seg;

    float* gh = nullptr; float* gq = nullptr; float* gxc = nullptr;
    float* gw1t = nullptr; float* gw2t = nullptr;
    cudaGetSymbolAddress((void**)&gh, g_hidden);
    cudaGetSymbolAddress((void**)&gq, g_q);
    cudaGetSymbolAddress((void**)&gxc, g_xc);
    cudaGetSymbolAddress((void**)&gw1t, g_w1t);
    cudaGetSymbolAddress((void**)&gw2t, g_w2t);
    float* gh0 = gh;
    float* gh1 = gh + (size_t)MROWS * HID;
    float* gh2 = gh + 2 * (size_t)MROWS * HID;
    float* w1t0 = gw1t;
    float* w1t1 = gw1t + (size_t)HID * DMODEL;
    float* w1t2 = gw1t + 2 * (size_t)HID * DMODEL;
    float* w2t0 = gw2t;
    float* w2t1 = gw2t + (size_t)DMODEL * HID;
    float* w2t2 = gw2t + 2 * (size_t)DMODEL * HID;

    cudaFuncSetAttribute(gemm_mma, cudaFuncAttributeMaxDynamicSharedMemorySize, SM_BYTES);
    cudaFuncSetAttribute(attention_mma, cudaFuncAttributeMaxDynamicSharedMemorySize, ATT_SMEM_BYTES);

    // Prepass: round x; transpose+round weights
    {
        int n4 = (MROWS * DMODEL) / 4;
        round_x_kernel<<<(n4 + 255) / 256, 256>>>(x, gxc, n4);
        dim3 tb(32, 8);
        transpose_round<<<dim3(HID / 32, DMODEL / 32, 3), tb>>>(qW1, kW1, vW1, w1t0, w1t1, w1t2, DMODEL, HID);
        transpose_round<<<dim3(DMODEL / 32, HID / 32, 3), tb>>>(qW2, kW2, vW2, w2t0, w2t1, w2t2, HID, DMODEL);
    }

    // Stage 1: hidden[z] = tf32round(gelu(x @ W1[z] + b1[z]))
    {
        dim3 g(HID / BN, MROWS / BM, 3);
        gemm_mma<<<g, 256, SM_BYTES>>>(gxc, gxc, gxc,
                                       w1t0, w1t1, w1t2,
                                       qb1, kb1, vb1,
                                       gh0, gh1, gh2,
                                       HID, DMODEL, (2) | (2 << 2) | (2 << 4));
    }
    // Stage 2: q = h0@qW2+qb2 ; k = h1@kW2+kb2 ; v = gelu(h2@vW2+vb2)
    {
        dim3 g(DMODEL / BN, MROWS / BM, 3);
        gemm_mma<<<g, 256, SM_BYTES>>>(gh0, gh1, gh2,
                                       w2t0, w2t1, w2t2,
                                       qb2, kb2, vb2,
                                       gq, k_out, v_out,
                                       DMODEL, HID, (0) | (0 << 2) | (1 << 4));
    }
    // Stage 3: attention (tensor cores)
    {
        dim3 ga(SEQ / 128, 2 * NHEADS);
        attention_mma<<<ga, 256, ATT_SMEM_BYTES>>>(gq, k_out, v_out, o_out);
    }
}

// round 7
// speedup vs baseline: 3.0846x; 1.0528x over previous
#include <cuda_runtime.h>
#include <math.h>
#include <stdint.h>

// ---------------------------------------------------------------------------
// Problem: x (2,2048,512); W1 (512,2048); W2 (2048,512); HEADS=8
// M = 4096 rows. Output = concat(k, v, out), each 4096*512 fp32.
// GEMMs + attention on mma.sync m16n8k8 tf32 (plain sm_100 target).
// ---------------------------------------------------------------------------
#define MROWS 4096
#define DMODEL 512
#define HID 2048
#define SEQ 2048
#define NHEADS 8
#define DHEAD 64

#define BM 128
#define BN 128
#define BKK 32
#define KSTRIDE 36   // padded smem stride (floats): conflict-free fragments

// Scratch (device globals: allocation-free rule)
__device__ __align__(16) float g_hidden[3][(size_t)MROWS * HID];
__device__ __align__(16) float g_q[(size_t)MROWS * DMODEL];
__device__ __align__(16) float g_xc[(size_t)MROWS * DMODEL];
__device__ __align__(16) float g_w1t[3][(size_t)HID * DMODEL];   // W1^T: (2048,512)
__device__ __align__(16) float g_w2t[3][(size_t)DMODEL * HID];   // W2^T: (512,2048)

// ----------------------------- helpers -------------------------------------
__device__ __forceinline__ uint32_t smem_u32(const void* p) {
    uint32_t a;
    asm("{ .reg .u64 t; cvta.to.shared.u64 t, %1; cvt.u32.u64 %0, t; }" : "=r"(a) : "l"(p));
    return a;
}
__device__ __forceinline__ void cp16(uint32_t saddr, const void* g) {
    asm volatile("cp.async.cg.shared.global [%0], [%1], 16;" :: "r"(saddr), "l"(g));
}
__device__ __forceinline__ float tf32r(float x) {
    uint32_t u;
    asm("cvt.rna.tf32.f32 %0, %1;" : "=r"(u) : "f"(x));
    return __uint_as_float(u);
}
__device__ __forceinline__ float gelu_f(float x) {
    float x3 = x * x * x;
    float t = tanhf(0.7978845608028654f * (x + 0.044715f * x3));
    return 0.5f * x * (1.0f + t);
}
__device__ __forceinline__ void mma_tf32(float* c, const uint32_t* a, const uint32_t* b) {
    asm volatile(
        "mma.sync.aligned.m16n8k8.row.col.f32.tf32.tf32.f32 "
        "{%0,%1,%2,%3}, {%4,%5,%6,%7}, {%8,%9}, {%0,%1,%2,%3};"
        : "+f"(c[0]), "+f"(c[1]), "+f"(c[2]), "+f"(c[3])
        : "r"(a[0]), "r"(a[1]), "r"(a[2]), "r"(a[3]), "r"(b[0]), "r"(b[1]));
}

// ---------------------------------------------------------------------------
// Prepass: round x to tf32
// ---------------------------------------------------------------------------
__global__ void round_x_kernel(const float* __restrict__ in, float* __restrict__ out, int n4) {
    int i = blockIdx.x * blockDim.x + threadIdx.x;
    if (i < n4) {
        float4 v = ((const float4*)in)[i];
        v.x = tf32r(v.x); v.y = tf32r(v.y); v.z = tf32r(v.z); v.w = tf32r(v.w);
        ((float4*)out)[i] = v;
    }
}

// ---------------------------------------------------------------------------
// Prepass: transpose + round weights. src R x C -> dst C x R (tf32-rounded).
// ---------------------------------------------------------------------------
__global__ void transpose_round(const float* __restrict__ s0, const float* __restrict__ s1,
                                const float* __restrict__ s2,
                                float* __restrict__ d0, float* __restrict__ d1,
                                float* __restrict__ d2, int R, int C) {
    __shared__ float tile[32][33];
    const int z = blockIdx.z;
    const float* src = (z == 0) ? s0 : (z == 1) ? s1 : s2;
    float* dst = (z == 0) ? d0 : (z == 1) ? d1 : d2;
    int tx = threadIdx.x, ty = threadIdx.y;
    int bx = blockIdx.x, by = blockIdx.y;
#pragma unroll
    for (int j = 0; j < 4; j++) {
        int r = by * 32 + ty + j * 8;
        int c = bx * 32 + tx;
        tile[ty + j * 8][tx] = tf32r(src[(size_t)r * C + c]);
    }
    __syncthreads();
#pragma unroll
    for (int j = 0; j < 4; j++) {
        int dr = bx * 32 + ty + j * 8;
        int dc = by * 32 + tx;
        dst[(size_t)dr * R + dc] = tile[tx][ty + j * 8];
    }
}

// ---------------------------------------------------------------------------
// Tensor-core tf32 GEMM (unchanged): C[z] = act(A[z] @ Bt[z]^T + b[z])
// ---------------------------------------------------------------------------
#define AS_OFF(buf) ((buf) * 4608u)
#define BS_OFF(buf) (9216u + (buf) * 4608u)
#define SM_BYTES (18432 * 4)

__global__ void __launch_bounds__(256, 2) gemm_mma(
    const float* __restrict__ A0, const float* __restrict__ A1, const float* __restrict__ A2,
    const float* __restrict__ B0, const float* __restrict__ B1, const float* __restrict__ B2,
    const float* __restrict__ bias0, const float* __restrict__ bias1, const float* __restrict__ bias2,
    float* __restrict__ C0, float* __restrict__ C1, float* __restrict__ C2,
    int N, int K, int actModes)
{
    extern __shared__ float smem[];
    const uint32_t sb = smem_u32(smem);

    const int z = blockIdx.z;
    const float* A = (z == 0) ? A0 : (z == 1) ? A1 : A2;
    const float* B = (z == 0) ? B0 : (z == 1) ? B1 : B2;
    const float* bias = (z == 0) ? bias0 : (z == 1) ? bias1 : bias2;
    float* C = (z == 0) ? C0 : (z == 1) ? C1 : C2;
    const int mode = (actModes >> (2 * z)) & 3;

    const int tid = threadIdx.x;
    const int wid = tid >> 5;
    const int lane = tid & 31;
    const int bm = blockIdx.y * BM;
    const int bn = blockIdx.x * BN;
    const int wm = (wid >> 2) * 64;
    const int wn = (wid & 3) * 32;

    const int lr = lane >> 2;
    const int lc = lane & 3;

    const int grow = tid >> 3;
    const int gc16 = tid & 7;

    float acc[4][4][4];
#pragma unroll
    for (int i = 0; i < 4; i++)
#pragma unroll
        for (int j = 0; j < 4; j++)
#pragma unroll
            for (int t = 0; t < 4; t++) acc[i][j][t] = 0.0f;

    auto loadTile = [&](int kc, int buf) {
        const float* ga = A + (size_t)(bm + grow) * K + kc * BKK + gc16 * 4;
        const float* gb = B + (size_t)(bn + grow) * K + kc * BKK + gc16 * 4;
        uint32_t sa = sb + AS_OFF(buf) * 4 + grow * (KSTRIDE * 4) + gc16 * 16;
        uint32_t sbb = sb + BS_OFF(buf) * 4 + grow * (KSTRIDE * 4) + gc16 * 16;
#pragma unroll
        for (int j = 0; j < 4; j++) {
            cp16(sa + j * 32 * (KSTRIDE * 4), ga + (size_t)(32 * j) * K);
            cp16(sbb + j * 32 * (KSTRIDE * 4), gb + (size_t)(32 * j) * K);
        }
        asm volatile("cp.async.commit_group;" ::: "memory");
    };

    const int NC = K / BKK;
    loadTile(0, 0);

    for (int c = 0; c < NC; c++) {
        const int b = c & 1;
        __syncthreads();
        if (c + 1 < NC) {
            loadTile(c + 1, b ^ 1);
            asm volatile("cp.async.wait_group 1;" ::: "memory");
        } else {
            asm volatile("cp.async.wait_group 0;" ::: "memory");
        }
        __syncthreads();

        const float* As = smem + AS_OFF(b);
        const float* Bs = smem + BS_OFF(b);
#pragma unroll
        for (int ks = 0; ks < 4; ks++) {
            const int k0 = ks * 8;
            uint32_t af[4][4], bf[4][2];
#pragma unroll
            for (int mt = 0; mt < 4; mt++) {
                int r = wm + mt * 16 + lr;
                const float* p = As + r * KSTRIDE + k0 + lc;
                af[mt][0] = __float_as_uint(p[0]);
                af[mt][1] = __float_as_uint(p[8 * KSTRIDE]);
                af[mt][2] = __float_as_uint(p[4]);
                af[mt][3] = __float_as_uint(p[8 * KSTRIDE + 4]);
            }
#pragma unroll
            for (int nt = 0; nt < 4; nt++) {
                int n = wn + nt * 8 + lr;
                const float* p = Bs + n * KSTRIDE + k0 + lc;
                bf[nt][0] = __float_as_uint(p[0]);
                bf[nt][1] = __float_as_uint(p[4]);
            }
#pragma unroll
            for (int mt = 0; mt < 4; mt++)
#pragma unroll
                for (int nt = 0; nt < 4; nt++)
                    mma_tf32(acc[mt][nt], af[mt], bf[nt]);
        }
    }

    float2 bv[4];
#pragma unroll
    for (int nt = 0; nt < 4; nt++) {
        int col = bn + wn + nt * 8 + 2 * lc;
        bv[nt] = *(const float2*)(bias + col);
    }
#pragma unroll
    for (int mt = 0; mt < 4; mt++) {
        int row0 = bm + wm + mt * 16 + lr;
#pragma unroll
        for (int nt = 0; nt < 4; nt++) {
            int col = bn + wn + nt * 8 + 2 * lc;
#pragma unroll
            for (int half = 0; half < 2; half++) {
                int row = row0 + half * 8;
                float v0 = acc[mt][nt][2 * half + 0] + bv[nt].x;
                float v1 = acc[mt][nt][2 * half + 1] + bv[nt].y;
                if (mode >= 1) { v0 = gelu_f(v0); v1 = gelu_f(v1); }
                if (mode == 2) { v0 = tf32r(v0); v1 = tf32r(v1); }
                *(float2*)(C + (size_t)row * N + col) = make_float2(v0, v1);
            }
        }
    }
}

// ---------------------------------------------------------------------------
// Tensor-core causal flash attention, v2: cp.async double-buffered K/V.
// CTA: 128 query rows of one (batch,head); 8 warps x 16 rows.
// K raw fp32, stride 68 (banks 4*lr+lc, conflict-free).
// V raw fp32 row-major, stride 72 (banks 8*lc+lr, conflict-free) — no transpose.
// HMMA truncates fp32->tf32 for K/V; Q pre-scaled by 0.125 and rna-rounded.
// One __syncthreads per key tile; loads for kt+1 overlap compute of kt.
// Smem (floats): Ps[128*68] | Ks[2][64*68] | Vs[2][64*72]
// ---------------------------------------------------------------------------
#define ATT_PS 0
#define ATT_KS 8704
#define ATT_VS 17408
#define ATT_KBUF 4352
#define ATT_VBUF 4608
#define ATT_SMEM_BYTES (26624 * 4)

__global__ void __launch_bounds__(256, 2) attention_mma(
    const float* __restrict__ Qg, const float* __restrict__ Kg,
    const float* __restrict__ Vg, float* __restrict__ Og)
{
    extern __shared__ float sm[];
    const uint32_t sb = smem_u32(sm);
    float* Ps = sm + ATT_PS;

    const int tid = threadIdx.x;
    const int wid = tid >> 5;
    const int lane = tid & 31;
    const int lr = lane >> 2;
    const int lc = lane & 3;
    const int qt = gridDim.x - 1 - blockIdx.x;   // heavy tiles first
    const int nb = blockIdx.y >> 3;
    const int h  = blockIdx.y & 7;
    const int bm = qt * 128;
    const int wm = wid * 16;

    const size_t base = ((size_t)nb * SEQ) * DMODEL + (size_t)h * DHEAD;

    auto loadKV = [&](int kt, int b) {
#pragma unroll
        for (int j = 0; j < 4; j++) {
            int c = tid + 256 * j;
            int r = c >> 4;                  // key row 0..63
            int q4 = (c & 15) * 4;           // dim 0..60 step 4
            size_t g = base + (size_t)(kt * 64 + r) * DMODEL + q4;
            cp16(sb + (ATT_KS + b * ATT_KBUF + r * 68 + q4) * 4, Kg + g);
            cp16(sb + (ATT_VS + b * ATT_VBUF + r * 72 + q4) * 4, Vg + g);
        }
        asm volatile("cp.async.commit_group;" ::: "memory");
    };

    // Start tile 0 loads immediately.
    loadKV(0, 0);

    // Stage Q (scaled by 1/sqrt(Dh)=0.125, rna-rounded) into Ps.
#pragma unroll
    for (int j = 0; j < 8; j++) {
        int idx = tid + 256 * j;
        int r = idx >> 4;
        int c = (idx & 15) * 4;
        float4 v = *(const float4*)(Qg + base + (size_t)(bm + r) * DMODEL + c);
        float* p = Ps + r * 68 + c;
        p[0] = tf32r(v.x * 0.125f); p[1] = tf32r(v.y * 0.125f);
        p[2] = tf32r(v.z * 0.125f); p[3] = tf32r(v.w * 0.125f);
    }
    __syncthreads();

    uint32_t qf[8][4];
#pragma unroll
    for (int ks = 0; ks < 8; ks++) {
        const float* p = Ps + (wm + lr) * 68 + ks * 8 + lc;
        qf[ks][0] = __float_as_uint(p[0]);
        qf[ks][1] = __float_as_uint(p[8 * 68]);
        qf[ks][2] = __float_as_uint(p[4]);
        qf[ks][3] = __float_as_uint(p[8 * 68 + 4]);
    }

    float of[8][4];
#pragma unroll
    for (int nf = 0; nf < 8; nf++)
#pragma unroll
        for (int t = 0; t < 4; t++) of[nf][t] = 0.0f;
    float m0 = -1e30f, m1 = -1e30f, l0 = 0.0f, l1 = 0.0f;

    const int r0g = bm + wm + lr;
    const int r1g = r0g + 8;
    const int ntiles = qt * 2 + 2;

    for (int kt = 0; kt < ntiles; kt++) {
        const int b = kt & 1;
        asm volatile("cp.async.wait_group 0;" ::: "memory");
        __syncthreads();   // tile kt visible CTA-wide; prev compute (reads of b^1) done
        if (kt + 1 < ntiles) loadKV(kt + 1, b ^ 1);

        const float* Ks = sm + ATT_KS + b * ATT_KBUF;
        const float* Vs = sm + ATT_VS + b * ATT_VBUF;

        // S = Q K^T  (warp rows x 64 keys); Q pre-scaled.
        float sf[8][4];
#pragma unroll
        for (int nf = 0; nf < 8; nf++)
#pragma unroll
            for (int t = 0; t < 4; t++) sf[nf][t] = 0.0f;
#pragma unroll
        for (int ks = 0; ks < 8; ks++) {
            uint32_t bf[8][2];
#pragma unroll
            for (int nf = 0; nf < 8; nf++) {
                const float* p = Ks + (nf * 8 + lr) * 68 + ks * 8 + lc;
                bf[nf][0] = __float_as_uint(p[0]);
                bf[nf][1] = __float_as_uint(p[4]);
            }
#pragma unroll
            for (int nf = 0; nf < 8; nf++)
                mma_tf32(sf[nf], qf[ks], bf[nf]);
        }

        // Causal mask (only last two tiles touch the diagonal)
        if (kt >= ntiles - 2) {
#pragma unroll
            for (int nf = 0; nf < 8; nf++) {
                int c0 = kt * 64 + nf * 8 + 2 * lc;
                if (c0     > r0g) sf[nf][0] = -1e30f;
                if (c0 + 1 > r0g) sf[nf][1] = -1e30f;
                if (c0     > r1g) sf[nf][2] = -1e30f;
                if (c0 + 1 > r1g) sf[nf][3] = -1e30f;
            }
        }

        // Online softmax; row stats live in a 4-lane quad.
        float mx0 = -1e30f, mx1 = -1e30f;
#pragma unroll
        for (int nf = 0; nf < 8; nf++) {
            mx0 = fmaxf(mx0, fmaxf(sf[nf][0], sf[nf][1]));
            mx1 = fmaxf(mx1, fmaxf(sf[nf][2], sf[nf][3]));
        }
        mx0 = fmaxf(mx0, __shfl_xor_sync(0xffffffffu, mx0, 1));
        mx0 = fmaxf(mx0, __shfl_xor_sync(0xffffffffu, mx0, 2));
        mx1 = fmaxf(mx1, __shfl_xor_sync(0xffffffffu, mx1, 1));
        mx1 = fmaxf(mx1, __shfl_xor_sync(0xffffffffu, mx1, 2));
        float mn0 = fmaxf(m0, mx0), mn1 = fmaxf(m1, mx1);
        float corr0 = __expf(m0 - mn0), corr1 = __expf(m1 - mn1);

        float rs0 = 0.0f, rs1 = 0.0f;
        float* pr0 = Ps + (wm + lr) * 68;
        float* pr1 = Ps + (wm + lr + 8) * 68;
#pragma unroll
        for (int nf = 0; nf < 8; nf++) {
            float p0 = __expf(sf[nf][0] - mn0);
            float p1 = __expf(sf[nf][1] - mn0);
            float p2 = __expf(sf[nf][2] - mn1);
            float p3 = __expf(sf[nf][3] - mn1);
            rs0 += p0 + p1;
            rs1 += p2 + p3;
            *(float2*)(pr0 + nf * 8 + 2 * lc) = make_float2(p0, p1);
            *(float2*)(pr1 + nf * 8 + 2 * lc) = make_float2(p2, p3);
        }
        rs0 += __shfl_xor_sync(0xffffffffu, rs0, 1);
        rs0 += __shfl_xor_sync(0xffffffffu, rs0, 2);
        rs1 += __shfl_xor_sync(0xffffffffu, rs1, 1);
        rs1 += __shfl_xor_sync(0xffffffffu, rs1, 2);
        l0 = l0 * corr0 + rs0;
        l1 = l1 * corr1 + rs1;
        m0 = mn0; m1 = mn1;
#pragma unroll
        for (int nf = 0; nf < 8; nf++) {
            of[nf][0] *= corr0; of[nf][1] *= corr0;
            of[nf][2] *= corr1; of[nf][3] *= corr1;
        }
        __syncwarp();   // P rows are warp-private: warp sync suffices

        // O += P V   (V row-major: B[k][n] = Vs[key][dim], stride 72)
#pragma unroll
        for (int ks = 0; ks < 8; ks++) {
            uint32_t af[4];
            const float* p = Ps + (wm + lr) * 68 + ks * 8 + lc;
            af[0] = __float_as_uint(p[0]);
            af[1] = __float_as_uint(p[8 * 68]);
            af[2] = __float_as_uint(p[4]);
            af[3] = __float_as_uint(p[8 * 68 + 4]);
#pragma unroll
            for (int nf = 0; nf < 8; nf++) {
                uint32_t bf2[2];
                const float* pv = Vs + (ks * 8 + lc) * 72 + nf * 8 + lr;
                bf2[0] = __float_as_uint(pv[0]);
                bf2[1] = __float_as_uint(pv[4 * 72]);
                mma_tf32(of[nf], af, bf2);
            }
        }
    }

    const float inv0 = 1.0f / l0;
    const float inv1 = 1.0f / l1;
#pragma unroll
    for (int nf = 0; nf < 8; nf++) {
        int col = nf * 8 + 2 * lc;
        *(float2*)(Og + base + (size_t)r0g * DMODEL + col) =
            make_float2(of[nf][0] * inv0, of[nf][1] * inv0);
        *(float2*)(Og + base + (size_t)r1g * DMODEL + col) =
            make_float2(of[nf][2] * inv1, of[nf][3] * inv1);
    }
}

// ---------------------------------------------------------------------------
extern "C" void kernel_launch(void* const* d_in, const int* in_sizes, int n_in,
                              void* d_out, int out_size) {
    const float* x   = (const float*)d_in[0];
    const float* qW1 = (const float*)d_in[1];
    const float* qb1 = (const float*)d_in[2];
    const float* qW2 = (const float*)d_in[3];
    const float* qb2 = (const float*)d_in[4];
    const float* kW1 = (const float*)d_in[5];
    const float* kb1 = (const float*)d_in[6];
    const float* kW2 = (const float*)d_in[7];
    const float* kb2 = (const float*)d_in[8];
    const float* vW1 = (const float*)d_in[9];
    const float* vb1 = (const float*)d_in[10];
    const float* vW2 = (const float*)d_in[11];
    const float* vb2 = (const float*)d_in[12];

    float* out = (float*)d_out;
    const size_t seg = (size_t)MROWS * DMODEL;
    float* k_out = out;
    float* v_out = out + seg;
    float* o_out = out + 2 * seg;

    float* gh = nullptr; float* gq = nullptr; float* gxc = nullptr;
    float* gw1t = nullptr; float* gw2t = nullptr;
    cudaGetSymbolAddress((void**)&gh, g_hidden);
    cudaGetSymbolAddress((void**)&gq, g_q);
    cudaGetSymbolAddress((void**)&gxc, g_xc);
    cudaGetSymbolAddress((void**)&gw1t, g_w1t);
    cudaGetSymbolAddress((void**)&gw2t, g_w2t);
    float* gh0 = gh;
    float* gh1 = gh + (size_t)MROWS * HID;
    float* gh2 = gh + 2 * (size_t)MROWS * HID;
    float* w1t0 = gw1t;
    float* w1t1 = gw1t + (size_t)HID * DMODEL;
    float* w1t2 = gw1t + 2 * (size_t)HID * DMODEL;
    float* w2t0 = gw2t;
    float* w2t1 = gw2t + (size_t)DMODEL * HID;
    float* w2t2 = gw2t + 2 * (size_t)DMODEL * HID;

    cudaFuncSetAttribute(gemm_mma, cudaFuncAttributeMaxDynamicSharedMemorySize, SM_BYTES);
    cudaFuncSetAttribute(attention_mma, cudaFuncAttributeMaxDynamicSharedMemorySize, ATT_SMEM_BYTES);

    // Prepass: round x; transpose+round weights
    {
        int n4 = (MROWS * DMODEL) / 4;
        round_x_kernel<<<(n4 + 255) / 256, 256>>>(x, gxc, n4);
        dim3 tb(32, 8);
        transpose_round<<<dim3(HID / 32, DMODEL / 32, 3), tb>>>(qW1, kW1, vW1, w1t0, w1t1, w1t2, DMODEL, HID);
        transpose_round<<<dim3(DMODEL / 32, HID / 32, 3), tb>>>(qW2, kW2, vW2, w2t0, w2t1, w2t2, HID, DMODEL);
    }

    // Stage 1: hidden[z] = tf32round(gelu(x @ W1[z] + b1[z]))
    {
        dim3 g(HID / BN, MROWS / BM, 3);
        gemm_mma<<<g, 256, SM_BYTES>>>(gxc, gxc, gxc,
                                       w1t0, w1t1, w1t2,
                                       qb1, kb1, vb1,
                                       gh0, gh1, gh2,
                                       HID, DMODEL, (2) | (2 << 2) | (2 << 4));
    }
    // Stage 2: q = h0@qW2+qb2 ; k = h1@kW2+kb2 ; v = gelu(h2@vW2+vb2)
    {
        dim3 g(DMODEL / BN, MROWS / BM, 3);
        gemm_mma<<<g, 256, SM_BYTES>>>(gh0, gh1, gh2,
                                       w2t0, w2t1, w2t2,
                                       qb2, kb2, vb2,
                                       gq, k_out, v_out,
                                       DMODEL, HID, (0) | (0 << 2) | (1 << 4));
    }
    // Stage 3: attention (tensor cores, pipelined)
    {
        dim3 ga(SEQ / 128, 2 * NHEADS);
        attention_mma<<<ga, 256, ATT_SMEM_BYTES>>>(gq, k_out, v_out, o_out);
    }
}

// round 8
// speedup vs baseline: 3.3224x; 1.0771x over previous
#include <cuda_runtime.h>
#include <math.h>
#include <stdint.h>

// ---------------------------------------------------------------------------
// Problem: x (2,2048,512); W1 (512,2048); W2 (2048,512); HEADS=8
// M = 4096 rows. Output = concat(k, v, out), each 4096*512 fp32.
// GEMMs + attention on mma.sync m16n8k8 tf32 (plain sm_100 target).
// R8: GEMM fragment loads via ldmatrix.x4 (b16 trick on tf32 data).
// ---------------------------------------------------------------------------
#define MROWS 4096
#define DMODEL 512
#define HID 2048
#define SEQ 2048
#define NHEADS 8
#define DHEAD 64

#define BM 128
#define BN 128
#define BKK 32
#define KSTRIDE 36   // padded smem stride (floats): 144B rows, 16B-aligned, conflict-free

// Scratch (device globals: allocation-free rule)
__device__ __align__(16) float g_hidden[3][(size_t)MROWS * HID];
__device__ __align__(16) float g_q[(size_t)MROWS * DMODEL];
__device__ __align__(16) float g_xc[(size_t)MROWS * DMODEL];
__device__ __align__(16) float g_w1t[3][(size_t)HID * DMODEL];   // W1^T: (2048,512)
__device__ __align__(16) float g_w2t[3][(size_t)DMODEL * HID];   // W2^T: (512,2048)

// ----------------------------- helpers -------------------------------------
__device__ __forceinline__ uint32_t smem_u32(const void* p) {
    uint32_t a;
    asm("{ .reg .u64 t; cvta.to.shared.u64 t, %1; cvt.u32.u64 %0, t; }" : "=r"(a) : "l"(p));
    return a;
}
__device__ __forceinline__ void cp16(uint32_t saddr, const void* g) {
    asm volatile("cp.async.cg.shared.global [%0], [%1], 16;" :: "r"(saddr), "l"(g));
}
__device__ __forceinline__ float tf32r(float x) {
    uint32_t u;
    asm("cvt.rna.tf32.f32 %0, %1;" : "=r"(u) : "f"(x));
    return __uint_as_float(u);
}
__device__ __forceinline__ float gelu_f(float x) {
    float x3 = x * x * x;
    float t = tanhf(0.7978845608028654f * (x + 0.044715f * x3));
    return 0.5f * x * (1.0f + t);
}
__device__ __forceinline__ void mma_tf32(float* c, const uint32_t* a, const uint32_t* b) {
    asm volatile(
        "mma.sync.aligned.m16n8k8.row.col.f32.tf32.tf32.f32 "
        "{%0,%1,%2,%3}, {%4,%5,%6,%7}, {%8,%9}, {%0,%1,%2,%3};"
        : "+f"(c[0]), "+f"(c[1]), "+f"(c[2]), "+f"(c[3])
        : "r"(a[0]), "r"(a[1]), "r"(a[2]), "r"(a[3]), "r"(b[0]), "r"(b[1]));
}
// ldmatrix x4 on 32-bit data: each m8n8.b16 tile = 8 rows x 4 tf32; lane l of
// tile gets element [l/4][l%4] — exactly the m16n8k8 tf32 fragment layout.
__device__ __forceinline__ void ldsm4(uint32_t* r, uint32_t addr) {
    asm volatile("ldmatrix.sync.aligned.m8n8.x4.shared.b16 {%0,%1,%2,%3}, [%4];"
        : "=r"(r[0]), "=r"(r[1]), "=r"(r[2]), "=r"(r[3]) : "r"(addr));
}

// ---------------------------------------------------------------------------
// Prepass: round x to tf32
// ---------------------------------------------------------------------------
__global__ void round_x_kernel(const float* __restrict__ in, float* __restrict__ out, int n4) {
    int i = blockIdx.x * blockDim.x + threadIdx.x;
    if (i < n4) {
        float4 v = ((const float4*)in)[i];
        v.x = tf32r(v.x); v.y = tf32r(v.y); v.z = tf32r(v.z); v.w = tf32r(v.w);
        ((float4*)out)[i] = v;
    }
}

// ---------------------------------------------------------------------------
// Prepass: transpose + round weights. src R x C -> dst C x R (tf32-rounded).
// ---------------------------------------------------------------------------
__global__ void transpose_round(const float* __restrict__ s0, const float* __restrict__ s1,
                                const float* __restrict__ s2,
                                float* __restrict__ d0, float* __restrict__ d1,
                                float* __restrict__ d2, int R, int C) {
    __shared__ float tile[32][33];
    const int z = blockIdx.z;
    const float* src = (z == 0) ? s0 : (z == 1) ? s1 : s2;
    float* dst = (z == 0) ? d0 : (z == 1) ? d1 : d2;
    int tx = threadIdx.x, ty = threadIdx.y;
    int bx = blockIdx.x, by = blockIdx.y;
#pragma unroll
    for (int j = 0; j < 4; j++) {
        int r = by * 32 + ty + j * 8;
        int c = bx * 32 + tx;
        tile[ty + j * 8][tx] = tf32r(src[(size_t)r * C + c]);
    }
    __syncthreads();
#pragma unroll
    for (int j = 0; j < 4; j++) {
        int dr = bx * 32 + ty + j * 8;
        int dc = by * 32 + tx;
        dst[(size_t)dr * R + dc] = tile[tx][ty + j * 8];
    }
}

// ---------------------------------------------------------------------------
// Tensor-core tf32 GEMM: C[z] = act(A[z] @ Bt[z]^T + b[z])
// 128x128x32 CTA tile, 8 warps (2 M x 4 N), warp tile 64x32.
// Fragment loads via ldmatrix.x4 (6 LDSM per k8-step vs 24 LDS.32).
// ---------------------------------------------------------------------------
#define AS_OFF(buf) ((buf) * 4608u)
#define BS_OFF(buf) (9216u + (buf) * 4608u)
#define SM_BYTES (18432 * 4)

__global__ void __launch_bounds__(256, 2) gemm_mma(
    const float* __restrict__ A0, const float* __restrict__ A1, const float* __restrict__ A2,
    const float* __restrict__ B0, const float* __restrict__ B1, const float* __restrict__ B2,
    const float* __restrict__ bias0, const float* __restrict__ bias1, const float* __restrict__ bias2,
    float* __restrict__ C0, float* __restrict__ C1, float* __restrict__ C2,
    int N, int K, int actModes)
{
    extern __shared__ float smem[];
    const uint32_t sb = smem_u32(smem);

    const int z = blockIdx.z;
    const float* A = (z == 0) ? A0 : (z == 1) ? A1 : A2;
    const float* B = (z == 0) ? B0 : (z == 1) ? B1 : B2;
    const float* bias = (z == 0) ? bias0 : (z == 1) ? bias1 : bias2;
    float* C = (z == 0) ? C0 : (z == 1) ? C1 : C2;
    const int mode = (actModes >> (2 * z)) & 3;

    const int tid = threadIdx.x;
    const int wid = tid >> 5;
    const int lane = tid & 31;
    const int bm = blockIdx.y * BM;
    const int bn = blockIdx.x * BN;
    const int wm = (wid >> 2) * 64;
    const int wn = (wid & 3) * 32;

    const int lr = lane >> 2;
    const int lc = lane & 3;

    const int grow = tid >> 3;
    const int gc16 = tid & 7;

    // Per-lane LDSM byte offsets within a buffer.
    // A (per mt): tiles {rows 0-7@k0, rows 8-15@k0, rows 0-7@k4, rows 8-15@k4}
    //   lane l -> row (l&15), col half (l>>4)*4.
    uint32_t aOff[4];
#pragma unroll
    for (int mt = 0; mt < 4; mt++)
        aOff[mt] = ((wm + mt * 16 + (lane & 15)) * KSTRIDE + ((lane >> 4) << 2)) * 4;
    // B (per nt-pair j): tiles {nt=2j@k0, nt=2j@k4, nt=2j+1@k0, nt=2j+1@k4}
    //   lane l -> n-row wn + (2j + (l>>4))*8 + (l&7), col half ((l>>3)&1)*4.
    uint32_t bOff[2];
#pragma unroll
    for (int j = 0; j < 2; j++)
        bOff[j] = ((wn + (2 * j + (lane >> 4)) * 8 + (lane & 7)) * KSTRIDE + (((lane >> 3) & 1) << 2)) * 4;

    float acc[4][4][4];
#pragma unroll
    for (int i = 0; i < 4; i++)
#pragma unroll
        for (int j = 0; j < 4; j++)
#pragma unroll
            for (int t = 0; t < 4; t++) acc[i][j][t] = 0.0f;

    auto loadTile = [&](int kc, int buf) {
        const float* ga = A + (size_t)(bm + grow) * K + kc * BKK + gc16 * 4;
        const float* gb = B + (size_t)(bn + grow) * K + kc * BKK + gc16 * 4;
        uint32_t sa = sb + AS_OFF(buf) * 4 + grow * (KSTRIDE * 4) + gc16 * 16;
        uint32_t sbb = sb + BS_OFF(buf) * 4 + grow * (KSTRIDE * 4) + gc16 * 16;
#pragma unroll
        for (int j = 0; j < 4; j++) {
            cp16(sa + j * 32 * (KSTRIDE * 4), ga + (size_t)(32 * j) * K);
            cp16(sbb + j * 32 * (KSTRIDE * 4), gb + (size_t)(32 * j) * K);
        }
        asm volatile("cp.async.commit_group;" ::: "memory");
    };

    const int NC = K / BKK;
    loadTile(0, 0);

    for (int c = 0; c < NC; c++) {
        const int b = c & 1;
        __syncthreads();
        if (c + 1 < NC) {
            loadTile(c + 1, b ^ 1);
            asm volatile("cp.async.wait_group 1;" ::: "memory");
        } else {
            asm volatile("cp.async.wait_group 0;" ::: "memory");
        }
        __syncthreads();

        const uint32_t sA = sb + AS_OFF(b) * 4;
        const uint32_t sB = sb + BS_OFF(b) * 4;
#pragma unroll
        for (int ks = 0; ks < 4; ks++) {
            const uint32_t kb = ks * 32;   // k0 * 4 bytes (8 floats per step)
            uint32_t af[4][4], bf[4][2];
#pragma unroll
            for (int mt = 0; mt < 4; mt++)
                ldsm4(af[mt], sA + aOff[mt] + kb);
#pragma unroll
            for (int j = 0; j < 2; j++) {
                uint32_t r[4];
                ldsm4(r, sB + bOff[j] + kb);
                bf[2 * j][0] = r[0]; bf[2 * j][1] = r[1];
                bf[2 * j + 1][0] = r[2]; bf[2 * j + 1][1] = r[3];
            }
#pragma unroll
            for (int mt = 0; mt < 4; mt++)
#pragma unroll
                for (int nt = 0; nt < 4; nt++)
                    mma_tf32(acc[mt][nt], af[mt], bf[nt]);
        }
    }

    float2 bv[4];
#pragma unroll
    for (int nt = 0; nt < 4; nt++) {
        int col = bn + wn + nt * 8 + 2 * lc;
        bv[nt] = *(const float2*)(bias + col);
    }
#pragma unroll
    for (int mt = 0; mt < 4; mt++) {
        int row0 = bm + wm + mt * 16 + lr;
#pragma unroll
        for (int nt = 0; nt < 4; nt++) {
            int col = bn + wn + nt * 8 + 2 * lc;
#pragma unroll
            for (int half = 0; half < 2; half++) {
                int row = row0 + half * 8;
                float v0 = acc[mt][nt][2 * half + 0] + bv[nt].x;
                float v1 = acc[mt][nt][2 * half + 1] + bv[nt].y;
                if (mode >= 1) { v0 = gelu_f(v0); v1 = gelu_f(v1); }
                if (mode == 2) { v0 = tf32r(v0); v1 = tf32r(v1); }
                *(float2*)(C + (size_t)row * N + col) = make_float2(v0, v1);
            }
        }
    }
}

// ---------------------------------------------------------------------------
// Tensor-core causal flash attention (unchanged from R7, 542.7us kernel).
// ---------------------------------------------------------------------------
#define ATT_PS 0
#define ATT_KS 8704
#define ATT_VS 17408
#define ATT_KBUF 4352
#define ATT_VBUF 4608
#define ATT_SMEM_BYTES (26624 * 4)

__global__ void __launch_bounds__(256, 2) attention_mma(
    const float* __restrict__ Qg, const float* __restrict__ Kg,
    const float* __restrict__ Vg, float* __restrict__ Og)
{
    extern __shared__ float sm[];
    const uint32_t sb = smem_u32(sm);
    float* Ps = sm + ATT_PS;

    const int tid = threadIdx.x;
    const int wid = tid >> 5;
    const int lane = tid & 31;
    const int lr = lane >> 2;
    const int lc = lane & 3;
    const int qt = gridDim.x - 1 - blockIdx.x;   // heavy tiles first
    const int nb = blockIdx.y >> 3;
    const int h  = blockIdx.y & 7;
    const int bm = qt * 128;
    const int wm = wid * 16;

    const size_t base = ((size_t)nb * SEQ) * DMODEL + (size_t)h * DHEAD;

    auto loadKV = [&](int kt, int b) {
#pragma unroll
        for (int j = 0; j < 4; j++) {
            int c = tid + 256 * j;
            int r = c >> 4;                  // key row 0..63
            int q4 = (c & 15) * 4;           // dim 0..60 step 4
            size_t g = base + (size_t)(kt * 64 + r) * DMODEL + q4;
            cp16(sb + (ATT_KS + b * ATT_KBUF + r * 68 + q4) * 4, Kg + g);
            cp16(sb + (ATT_VS + b * ATT_VBUF + r * 72 + q4) * 4, Vg + g);
        }
        asm volatile("cp.async.commit_group;" ::: "memory");
    };

    loadKV(0, 0);

    // Stage Q (scaled by 1/sqrt(Dh)=0.125, rna-rounded) into Ps.
#pragma unroll
    for (int j = 0; j < 8; j++) {
        int idx = tid + 256 * j;
        int r = idx >> 4;
        int c = (idx & 15) * 4;
        float4 v = *(const float4*)(Qg + base + (size_t)(bm + r) * DMODEL + c);
        float* p = Ps + r * 68 + c;
        p[0] = tf32r(v.x * 0.125f); p[1] = tf32r(v.y * 0.125f);
        p[2] = tf32r(v.z * 0.125f); p[3] = tf32r(v.w * 0.125f);
    }
    __syncthreads();

    uint32_t qf[8][4];
#pragma unroll
    for (int ks = 0; ks < 8; ks++) {
        const float* p = Ps + (wm + lr) * 68 + ks * 8 + lc;
        qf[ks][0] = __float_as_uint(p[0]);
        qf[ks][1] = __float_as_uint(p[8 * 68]);
        qf[ks][2] = __float_as_uint(p[4]);
        qf[ks][3] = __float_as_uint(p[8 * 68 + 4]);
    }

    float of[8][4];
#pragma unroll
    for (int nf = 0; nf < 8; nf++)
#pragma unroll
        for (int t = 0; t < 4; t++) of[nf][t] = 0.0f;
    float m0 = -1e30f, m1 = -1e30f, l0 = 0.0f, l1 = 0.0f;

    const int r0g = bm + wm + lr;
    const int r1g = r0g + 8;
    const int ntiles = qt * 2 + 2;

    for (int kt = 0; kt < ntiles; kt++) {
        const int b = kt & 1;
        asm volatile("cp.async.wait_group 0;" ::: "memory");
        __syncthreads();
        if (kt + 1 < ntiles) loadKV(kt + 1, b ^ 1);

        const float* Ks = sm + ATT_KS + b * ATT_KBUF;
        const float* Vs = sm + ATT_VS + b * ATT_VBUF;

        float sf[8][4];
#pragma unroll
        for (int nf = 0; nf < 8; nf++)
#pragma unroll
            for (int t = 0; t < 4; t++) sf[nf][t] = 0.0f;
#pragma unroll
        for (int ks = 0; ks < 8; ks++) {
            uint32_t bf[8][2];
#pragma unroll
            for (int nf = 0; nf < 8; nf++) {
                const float* p = Ks + (nf * 8 + lr) * 68 + ks * 8 + lc;
                bf[nf][0] = __float_as_uint(p[0]);
                bf[nf][1] = __float_as_uint(p[4]);
            }
#pragma unroll
            for (int nf = 0; nf < 8; nf++)
                mma_tf32(sf[nf], qf[ks], bf[nf]);
        }

        if (kt >= ntiles - 2) {
#pragma unroll
            for (int nf = 0; nf < 8; nf++) {
                int c0 = kt * 64 + nf * 8 + 2 * lc;
                if (c0     > r0g) sf[nf][0] = -1e30f;
                if (c0 + 1 > r0g) sf[nf][1] = -1e30f;
                if (c0     > r1g) sf[nf][2] = -1e30f;
                if (c0 + 1 > r1g) sf[nf][3] = -1e30f;
            }
        }

        float mx0 = -1e30f, mx1 = -1e30f;
#pragma unroll
        for (int nf = 0; nf < 8; nf++) {
            mx0 = fmaxf(mx0, fmaxf(sf[nf][0], sf[nf][1]));
            mx1 = fmaxf(mx1, fmaxf(sf[nf][2], sf[nf][3]));
        }
        mx0 = fmaxf(mx0, __shfl_xor_sync(0xffffffffu, mx0, 1));
        mx0 = fmaxf(mx0, __shfl_xor_sync(0xffffffffu, mx0, 2));
        mx1 = fmaxf(mx1, __shfl_xor_sync(0xffffffffu, mx1, 1));
        mx1 = fmaxf(mx1, __shfl_xor_sync(0xffffffffu, mx1, 2));
        float mn0 = fmaxf(m0, mx0), mn1 = fmaxf(m1, mx1);
        float corr0 = __expf(m0 - mn0), corr1 = __expf(m1 - mn1);

        float rs0 = 0.0f, rs1 = 0.0f;
        float* pr0 = Ps + (wm + lr) * 68;
        float* pr1 = Ps + (wm + lr + 8) * 68;
#pragma unroll
        for (int nf = 0; nf < 8; nf++) {
            float p0 = __expf(sf[nf][0] - mn0);
            float p1 = __expf(sf[nf][1] - mn0);
            float p2 = __expf(sf[nf][2] - mn1);
            float p3 = __expf(sf[nf][3] - mn1);
            rs0 += p0 + p1;
            rs1 += p2 + p3;
            *(float2*)(pr0 + nf * 8 + 2 * lc) = make_float2(p0, p1);
            *(float2*)(pr1 + nf * 8 + 2 * lc) = make_float2(p2, p3);
        }
        rs0 += __shfl_xor_sync(0xffffffffu, rs0, 1);
        rs0 += __shfl_xor_sync(0xffffffffu, rs0, 2);
        rs1 += __shfl_xor_sync(0xffffffffu, rs1, 1);
        rs1 += __shfl_xor_sync(0xffffffffu, rs1, 2);
        l0 = l0 * corr0 + rs0;
        l1 = l1 * corr1 + rs1;
        m0 = mn0; m1 = mn1;
#pragma unroll
        for (int nf = 0; nf < 8; nf++) {
            of[nf][0] *= corr0; of[nf][1] *= corr0;
            of[nf][2] *= corr1; of[nf][3] *= corr1;
        }
        __syncwarp();

#pragma unroll
        for (int ks = 0; ks < 8; ks++) {
            uint32_t af[4];
            const float* p = Ps + (wm + lr) * 68 + ks * 8 + lc;
            af[0] = __float_as_uint(p[0]);
            af[1] = __float_as_uint(p[8 * 68]);
            af[2] = __float_as_uint(p[4]);
            af[3] = __float_as_uint(p[8 * 68 + 4]);
#pragma unroll
            for (int nf = 0; nf < 8; nf++) {
                uint32_t bf2[2];
                const float* pv = Vs + (ks * 8 + lc) * 72 + nf * 8 + lr;
                bf2[0] = __float_as_uint(pv[0]);
                bf2[1] = __float_as_uint(pv[4 * 72]);
                mma_tf32(of[nf], af, bf2);
            }
        }
    }

    const float inv0 = 1.0f / l0;
    const float inv1 = 1.0f / l1;
#pragma unroll
    for (int nf = 0; nf < 8; nf++) {
        int col = nf * 8 + 2 * lc;
        *(float2*)(Og + base + (size_t)r0g * DMODEL + col) =
            make_float2(of[nf][0] * inv0, of[nf][1] * inv0);
        *(float2*)(Og + base + (size_t)r1g * DMODEL + col) =
            make_float2(of[nf][2] * inv1, of[nf][3] * inv1);
    }
}

// ---------------------------------------------------------------------------
extern "C" void kernel_launch(void* const* d_in, const int* in_sizes, int n_in,
                              void* d_out, int out_size) {
    const float* x   = (const float*)d_in[0];
    const float* qW1 = (const float*)d_in[1];
    const float* qb1 = (const float*)d_in[2];
    const float* qW2 = (const float*)d_in[3];
    const float* qb2 = (const float*)d_in[4];
    const float* kW1 = (const float*)d_in[5];
    const float* kb1 = (const float*)d_in[6];
    const float* kW2 = (const float*)d_in[7];
    const float* kb2 = (const float*)d_in[8];
    const float* vW1 = (const float*)d_in[9];
    const float* vb1 = (const float*)d_in[10];
    const float* vW2 = (const float*)d_in[11];
    const float* vb2 = (const float*)d_in[12];

    float* out = (float*)d_out;
    const size_t seg = (size_t)MROWS * DMODEL;
    float* k_out = out;
    float* v_out = out + seg;
    float* o_out = out + 2 * seg;

    float* gh = nullptr; float* gq = nullptr; float* gxc = nullptr;
    float* gw1t = nullptr; float* gw2t = nullptr;
    cudaGetSymbolAddress((void**)&gh, g_hidden);
    cudaGetSymbolAddress((void**)&gq, g_q);
    cudaGetSymbolAddress((void**)&gxc, g_xc);
    cudaGetSymbolAddress((void**)&gw1t, g_w1t);
    cudaGetSymbolAddress((void**)&gw2t, g_w2t);
    float* gh0 = gh;
    float* gh1 = gh + (size_t)MROWS * HID;
    float* gh2 = gh + 2 * (size_t)MROWS * HID;
    float* w1t0 = gw1t;
    float* w1t1 = gw1t + (size_t)HID * DMODEL;
    float* w1t2 = gw1t + 2 * (size_t)HID * DMODEL;
    float* w2t0 = gw2t;
    float* w2t1 = gw2t + (size_t)DMODEL * HID;
    float* w2t2 = gw2t + 2 * (size_t)DMODEL * HID;

    cudaFuncSetAttribute(gemm_mma, cudaFuncAttributeMaxDynamicSharedMemorySize, SM_BYTES);
    cudaFuncSetAttribute(attention_mma, cudaFuncAttributeMaxDynamicSharedMemorySize, ATT_SMEM_BYTES);

    // Prepass: round x; transpose+round weights
    {
        int n4 = (MROWS * DMODEL) / 4;
        round_x_kernel<<<(n4 + 255) / 256, 256>>>(x, gxc, n4);
        dim3 tb(32, 8);
        transpose_round<<<dim3(HID / 32, DMODEL / 32, 3), tb>>>(qW1, kW1, vW1, w1t0, w1t1, w1t2, DMODEL, HID);
        transpose_round<<<dim3(DMODEL / 32, HID / 32, 3), tb>>>(qW2, kW2, vW2, w2t0, w2t1, w2t2, HID, DMODEL);
    }

    // Stage 1: hidden[z] = tf32round(gelu(x @ W1[z] + b1[z]))
    {
        dim3 g(HID / BN, MROWS / BM, 3);
        gemm_mma<<<g, 256, SM_BYTES>>>(gxc, gxc, gxc,
                                       w1t0, w1t1, w1t2,
                                       qb1, kb1, vb1,
                                       gh0, gh1, gh2,
                                       HID, DMODEL, (2) | (2 << 2) | (2 << 4));
    }
    // Stage 2: q = h0@qW2+qb2 ; k = h1@kW2+kb2 ; v = gelu(h2@vW2+vb2)
    {
        dim3 g(DMODEL / BN, MROWS / BM, 3);
        gemm_mma<<<g, 256, SM_BYTES>>>(gh0, gh1, gh2,
                                       w2t0, w2t1, w2t2,
                                       qb2, kb2, vb2,
                                       gq, k_out, v_out,
                                       DMODEL, HID, (0) | (0 << 2) | (1 << 4));
    }
    // Stage 3: attention (tensor cores, pipelined)
    {
        dim3 ga(SEQ / 128, 2 * NHEADS);
        attention_mma<<<ga, 256, ATT_SMEM_BYTES>>>(gq, k_out, v_out, o_out);
    }
}

// round 9
// speedup vs baseline: 4.4825x; 1.3492x over previous
#include <cuda_runtime.h>
#include <cuda_fp16.h>
#include <math.h>
#include <stdint.h>

// ---------------------------------------------------------------------------
// Problem: x (2,2048,512); W1 (512,2048); W2 (2048,512); HEADS=8
// M = 4096 rows. Output = concat(k, v, out), each 4096*512 fp32.
// R9: GEMMs on mma.sync m16n8k16 fp16 (same 10-bit mantissa as tf32, 2x rate,
// half the traffic). Attention unchanged (tf32 mma, cp.async pipelined).
// ---------------------------------------------------------------------------
#define MROWS 4096
#define DMODEL 512
#define HID 2048
#define SEQ 2048
#define NHEADS 8
#define DHEAD 64

#define BM 128
#define BN 128
#define BKK 32          // K elements per chunk (2 x k16 steps)
#define HSTRIDE 40      // smem row stride in halves (80B: conflict-free ldmatrix)

// Scratch (device globals: allocation-free rule)
__device__ __align__(16) __half g_hh[3][(size_t)MROWS * HID];     // hidden, fp16
__device__ __align__(16) __half g_xh[(size_t)MROWS * DMODEL];     // x, fp16
__device__ __align__(16) __half g_w1t[3][(size_t)HID * DMODEL];   // W1^T fp16
__device__ __align__(16) __half g_w2t[3][(size_t)DMODEL * HID];   // W2^T fp16
__device__ __align__(16) float  g_q[(size_t)MROWS * DMODEL];      // q, fp32

// ----------------------------- helpers -------------------------------------
__device__ __forceinline__ uint32_t smem_u32(const void* p) {
    uint32_t a;
    asm("{ .reg .u64 t; cvta.to.shared.u64 t, %1; cvt.u32.u64 %0, t; }" : "=r"(a) : "l"(p));
    return a;
}
__device__ __forceinline__ void cp16(uint32_t saddr, const void* g) {
    asm volatile("cp.async.cg.shared.global [%0], [%1], 16;" :: "r"(saddr), "l"(g));
}
__device__ __forceinline__ float tf32r(float x) {
    uint32_t u;
    asm("cvt.rna.tf32.f32 %0, %1;" : "=r"(u) : "f"(x));
    return __uint_as_float(u);
}
__device__ __forceinline__ float gelu_f(float x) {
    float x3 = x * x * x;
    float t = tanhf(0.7978845608028654f * (x + 0.044715f * x3));
    return 0.5f * x * (1.0f + t);
}
__device__ __forceinline__ void mma_tf32(float* c, const uint32_t* a, const uint32_t* b) {
    asm volatile(
        "mma.sync.aligned.m16n8k8.row.col.f32.tf32.tf32.f32 "
        "{%0,%1,%2,%3}, {%4,%5,%6,%7}, {%8,%9}, {%0,%1,%2,%3};"
        : "+f"(c[0]), "+f"(c[1]), "+f"(c[2]), "+f"(c[3])
        : "r"(a[0]), "r"(a[1]), "r"(a[2]), "r"(a[3]), "r"(b[0]), "r"(b[1]));
}
__device__ __forceinline__ void mma_f16(float* c, const uint32_t* a, const uint32_t* b) {
    asm volatile(
        "mma.sync.aligned.m16n8k16.row.col.f32.f16.f16.f32 "
        "{%0,%1,%2,%3}, {%4,%5,%6,%7}, {%8,%9}, {%0,%1,%2,%3};"
        : "+f"(c[0]), "+f"(c[1]), "+f"(c[2]), "+f"(c[3])
        : "r"(a[0]), "r"(a[1]), "r"(a[2]), "r"(a[3]), "r"(b[0]), "r"(b[1]));
}
__device__ __forceinline__ void ldsm4(uint32_t* r, uint32_t addr) {
    asm volatile("ldmatrix.sync.aligned.m8n8.x4.shared.b16 {%0,%1,%2,%3}, [%4];"
        : "=r"(r[0]), "=r"(r[1]), "=r"(r[2]), "=r"(r[3]) : "r"(addr));
}

// ---------------------------------------------------------------------------
// Prepass: convert x to fp16
// ---------------------------------------------------------------------------
__global__ void cvt_x_kernel(const float* __restrict__ in, __half* __restrict__ out, int n4) {
    int i = blockIdx.x * blockDim.x + threadIdx.x;
    if (i < n4) {
        float4 v = ((const float4*)in)[i];
        __half2 h0 = __floats2half2_rn(v.x, v.y);
        __half2 h1 = __floats2half2_rn(v.z, v.w);
        ((uint2*)out)[i] = make_uint2(*(uint32_t*)&h0, *(uint32_t*)&h1);
    }
}

// ---------------------------------------------------------------------------
// Prepass: transpose weights to fp16. src R x C fp32 -> dst C x R fp16.
// ---------------------------------------------------------------------------
__global__ void transpose_h(const float* __restrict__ s0, const float* __restrict__ s1,
                            const float* __restrict__ s2,
                            __half* __restrict__ d0, __half* __restrict__ d1,
                            __half* __restrict__ d2, int R, int C) {
    __shared__ float tile[32][33];
    const int z = blockIdx.z;
    const float* src = (z == 0) ? s0 : (z == 1) ? s1 : s2;
    __half* dst = (z == 0) ? d0 : (z == 1) ? d1 : d2;
    int tx = threadIdx.x, ty = threadIdx.y;
    int bx = blockIdx.x, by = blockIdx.y;
#pragma unroll
    for (int j = 0; j < 4; j++) {
        int r = by * 32 + ty + j * 8;
        int c = bx * 32 + tx;
        tile[ty + j * 8][tx] = src[(size_t)r * C + c];
    }
    __syncthreads();
#pragma unroll
    for (int j = 0; j < 4; j++) {
        int dr = bx * 32 + ty + j * 8;
        int dc = by * 32 + tx;
        dst[(size_t)dr * R + dc] = __float2half_rn(tile[tx][ty + j * 8]);
    }
}

// ---------------------------------------------------------------------------
// fp16 tensor-core GEMM: C[z] = act(A[z] @ Bt[z]^T + b[z])
// A: M x K fp16 row-major; Bt: N x K fp16 (W^T). 128x128x32 tile, 8 warps.
// mode per z (2 bits): 0 = none (fp32 out), 1 = gelu (fp32 out),
//                      2 = gelu (fp16 out).
// Smem: rows of HSTRIDE=40 halves (80B). ldmatrix tiles conflict-free
// (row shift 80B = 20 banks; 8 rows cover 32 banks exactly once).
// ---------------------------------------------------------------------------
#define GA_OFF(buf) ((buf) * 10240u)
#define GB_OFF(buf) (20480u + (buf) * 10240u)
#define SM_BYTES 40960

__global__ void __launch_bounds__(256, 2) gemm_mma(
    const __half* __restrict__ A0, const __half* __restrict__ A1, const __half* __restrict__ A2,
    const __half* __restrict__ B0, const __half* __restrict__ B1, const __half* __restrict__ B2,
    const float* __restrict__ bias0, const float* __restrict__ bias1, const float* __restrict__ bias2,
    void* __restrict__ C0, void* __restrict__ C1, void* __restrict__ C2,
    int N, int K, int actModes)
{
    extern __shared__ char smem[];
    const uint32_t sb = smem_u32(smem);

    const int z = blockIdx.z;
    const __half* A = (z == 0) ? A0 : (z == 1) ? A1 : A2;
    const __half* B = (z == 0) ? B0 : (z == 1) ? B1 : B2;
    const float* bias = (z == 0) ? bias0 : (z == 1) ? bias1 : bias2;
    void* C = (z == 0) ? C0 : (z == 1) ? C1 : C2;
    const int mode = (actModes >> (2 * z)) & 3;

    const int tid = threadIdx.x;
    const int wid = tid >> 5;
    const int lane = tid & 31;
    const int bm = blockIdx.y * BM;
    const int bn = blockIdx.x * BN;
    const int wm = (wid >> 2) * 64;
    const int wn = (wid & 3) * 32;

    const int lr = lane >> 2;
    const int lc = lane & 3;

    // Global-load mapping: 128 rows x 4 16B-chunks per operand; 2 per thread.
    const int grow = tid >> 2;       // 0..63 (+64)
    const int gchunk = tid & 3;      // 16B chunk (8 halves)

    // ldmatrix lane offsets (bytes within operand tile).
    // A (per mt, m16xk16): lanes 0-15 -> rows, lanes 16-31 -> +16B (k8..15).
    uint32_t aOff[4];
#pragma unroll
    for (int mt = 0; mt < 4; mt++)
        aOff[mt] = (uint32_t)(wm + mt * 16 + (lane & 15)) * (HSTRIDE * 2) + ((lane >> 4) << 4);
    // B (per nt-pair j): lanes 0-7 nt=2j k0-7; 8-15 nt=2j k8-15; 16-31 nt=2j+1.
    uint32_t bOff[2];
#pragma unroll
    for (int j = 0; j < 2; j++)
        bOff[j] = (uint32_t)(wn + (2 * j + (lane >> 4)) * 8 + (lane & 7)) * (HSTRIDE * 2) + (((lane >> 3) & 1) << 4);

    float acc[4][4][4];
#pragma unroll
    for (int i = 0; i < 4; i++)
#pragma unroll
        for (int j = 0; j < 4; j++)
#pragma unroll
            for (int t = 0; t < 4; t++) acc[i][j][t] = 0.0f;

    auto loadTile = [&](int kc, int buf) {
#pragma unroll
        for (int j = 0; j < 2; j++) {
            int r = grow + 64 * j;
            cp16(sb + GA_OFF(buf) + (uint32_t)r * (HSTRIDE * 2) + gchunk * 16,
                 A + (size_t)(bm + r) * K + kc * BKK + gchunk * 8);
            cp16(sb + GB_OFF(buf) + (uint32_t)r * (HSTRIDE * 2) + gchunk * 16,
                 B + (size_t)(bn + r) * K + kc * BKK + gchunk * 8);
        }
        asm volatile("cp.async.commit_group;" ::: "memory");
    };

    const int NC = K / BKK;
    loadTile(0, 0);

    for (int c = 0; c < NC; c++) {
        const int b = c & 1;
        __syncthreads();
        if (c + 1 < NC) {
            loadTile(c + 1, b ^ 1);
            asm volatile("cp.async.wait_group 1;" ::: "memory");
        } else {
            asm volatile("cp.async.wait_group 0;" ::: "memory");
        }
        __syncthreads();

        const uint32_t sA = sb + GA_OFF(b);
        const uint32_t sB = sb + GB_OFF(b);
#pragma unroll
        for (int kk = 0; kk < 2; kk++) {     // two k16 steps per 32-elt chunk
            const uint32_t kb = kk * 32;     // 16 halves = 32 bytes
            uint32_t af[4][4], bf[4][2];
#pragma unroll
            for (int mt = 0; mt < 4; mt++)
                ldsm4(af[mt], sA + aOff[mt] + kb);
#pragma unroll
            for (int j = 0; j < 2; j++) {
                uint32_t r[4];
                ldsm4(r, sB + bOff[j] + kb);
                bf[2 * j][0] = r[0]; bf[2 * j][1] = r[1];
                bf[2 * j + 1][0] = r[2]; bf[2 * j + 1][1] = r[3];
            }
#pragma unroll
            for (int mt = 0; mt < 4; mt++)
#pragma unroll
                for (int nt = 0; nt < 4; nt++)
                    mma_f16(acc[mt][nt], af[mt], bf[nt]);
        }
    }

    float2 bv[4];
#pragma unroll
    for (int nt = 0; nt < 4; nt++) {
        int col = bn + wn + nt * 8 + 2 * lc;
        bv[nt] = *(const float2*)(bias + col);
    }
#pragma unroll
    for (int mt = 0; mt < 4; mt++) {
        int row0 = bm + wm + mt * 16 + lr;
#pragma unroll
        for (int nt = 0; nt < 4; nt++) {
            int col = bn + wn + nt * 8 + 2 * lc;
#pragma unroll
            for (int half = 0; half < 2; half++) {
                int row = row0 + half * 8;
                float v0 = acc[mt][nt][2 * half + 0] + bv[nt].x;
                float v1 = acc[mt][nt][2 * half + 1] + bv[nt].y;
                if (mode >= 1) { v0 = gelu_f(v0); v1 = gelu_f(v1); }
                if (mode == 2) {
                    __half2 h = __floats2half2_rn(v0, v1);
                    *(__half2*)((__half*)C + (size_t)row * N + col) = h;
                } else {
                    *(float2*)((float*)C + (size_t)row * N + col) = make_float2(v0, v1);
                }
            }
        }
    }
}

// ---------------------------------------------------------------------------
// Tensor-core causal flash attention (unchanged from 503.9us kernel).
// ---------------------------------------------------------------------------
#define ATT_PS 0
#define ATT_KS 8704
#define ATT_VS 17408
#define ATT_KBUF 4352
#define ATT_VBUF 4608
#define ATT_SMEM_BYTES (26624 * 4)

__global__ void __launch_bounds__(256, 2) attention_mma(
    const float* __restrict__ Qg, const float* __restrict__ Kg,
    const float* __restrict__ Vg, float* __restrict__ Og)
{
    extern __shared__ float sm[];
    const uint32_t sb = smem_u32(sm);
    float* Ps = sm + ATT_PS;

    const int tid = threadIdx.x;
    const int wid = tid >> 5;
    const int lane = tid & 31;
    const int lr = lane >> 2;
    const int lc = lane & 3;
    const int qt = gridDim.x - 1 - blockIdx.x;   // heavy tiles first
    const int nb = blockIdx.y >> 3;
    const int h  = blockIdx.y & 7;
    const int bm = qt * 128;
    const int wm = wid * 16;

    const size_t base = ((size_t)nb * SEQ) * DMODEL + (size_t)h * DHEAD;

    auto loadKV = [&](int kt, int b) {
#pragma unroll
        for (int j = 0; j < 4; j++) {
            int c = tid + 256 * j;
            int r = c >> 4;
            int q4 = (c & 15) * 4;
            size_t g = base + (size_t)(kt * 64 + r) * DMODEL + q4;
            cp16(sb + (ATT_KS + b * ATT_KBUF + r * 68 + q4) * 4, Kg + g);
            cp16(sb + (ATT_VS + b * ATT_VBUF + r * 72 + q4) * 4, Vg + g);
        }
        asm volatile("cp.async.commit_group;" ::: "memory");
    };

    loadKV(0, 0);

#pragma unroll
    for (int j = 0; j < 8; j++) {
        int idx = tid + 256 * j;
        int r = idx >> 4;
        int c = (idx & 15) * 4;
        float4 v = *(const float4*)(Qg + base + (size_t)(bm + r) * DMODEL + c);
        float* p = Ps + r * 68 + c;
        p[0] = tf32r(v.x * 0.125f); p[1] = tf32r(v.y * 0.125f);
        p[2] = tf32r(v.z * 0.125f); p[3] = tf32r(v.w * 0.125f);
    }
    __syncthreads();

    uint32_t qf[8][4];
#pragma unroll
    for (int ks = 0; ks < 8; ks++) {
        const float* p = Ps + (wm + lr) * 68 + ks * 8 + lc;
        qf[ks][0] = __float_as_uint(p[0]);
        qf[ks][1] = __float_as_uint(p[8 * 68]);
        qf[ks][2] = __float_as_uint(p[4]);
        qf[ks][3] = __float_as_uint(p[8 * 68 + 4]);
    }

    float of[8][4];
#pragma unroll
    for (int nf = 0; nf < 8; nf++)
#pragma unroll
        for (int t = 0; t < 4; t++) of[nf][t] = 0.0f;
    float m0 = -1e30f, m1 = -1e30f, l0 = 0.0f, l1 = 0.0f;

    const int r0g = bm + wm + lr;
    const int r1g = r0g + 8;
    const int ntiles = qt * 2 + 2;

    for (int kt = 0; kt < ntiles; kt++) {
        const int b = kt & 1;
        asm volatile("cp.async.wait_group 0;" ::: "memory");
        __syncthreads();
        if (kt + 1 < ntiles) loadKV(kt + 1, b ^ 1);

        const float* Ks = sm + ATT_KS + b * ATT_KBUF;
        const float* Vs = sm + ATT_VS + b * ATT_VBUF;

        float sf[8][4];
#pragma unroll
        for (int nf = 0; nf < 8; nf++)
#pragma unroll
            for (int t = 0; t < 4; t++) sf[nf][t] = 0.0f;
#pragma unroll
        for (int ks = 0; ks < 8; ks++) {
            uint32_t bf[8][2];
#pragma unroll
            for (int nf = 0; nf < 8; nf++) {
                const float* p = Ks + (nf * 8 + lr) * 68 + ks * 8 + lc;
                bf[nf][0] = __float_as_uint(p[0]);
                bf[nf][1] = __float_as_uint(p[4]);
            }
#pragma unroll
            for (int nf = 0; nf < 8; nf++)
                mma_tf32(sf[nf], qf[ks], bf[nf]);
        }

        if (kt >= ntiles - 2) {
#pragma unroll
            for (int nf = 0; nf < 8; nf++) {
                int c0 = kt * 64 + nf * 8 + 2 * lc;
                if (c0     > r0g) sf[nf][0] = -1e30f;
                if (c0 + 1 > r0g) sf[nf][1] = -1e30f;
                if (c0     > r1g) sf[nf][2] = -1e30f;
                if (c0 + 1 > r1g) sf[nf][3] = -1e30f;
            }
        }

        float mx0 = -1e30f, mx1 = -1e30f;
#pragma unroll
        for (int nf = 0; nf < 8; nf++) {
            mx0 = fmaxf(mx0, fmaxf(sf[nf][0], sf[nf][1]));
            mx1 = fmaxf(mx1, fmaxf(sf[nf][2], sf[nf][3]));
        }
        mx0 = fmaxf(mx0, __shfl_xor_sync(0xffffffffu, mx0, 1));
        mx0 = fmaxf(mx0, __shfl_xor_sync(0xffffffffu, mx0, 2));
        mx1 = fmaxf(mx1, __shfl_xor_sync(0xffffffffu, mx1, 1));
        mx1 = fmaxf(mx1, __shfl_xor_sync(0xffffffffu, mx1, 2));
        float mn0 = fmaxf(m0, mx0), mn1 = fmaxf(m1, mx1);
        float corr0 = __expf(m0 - mn0), corr1 = __expf(m1 - mn1);

        float rs0 = 0.0f, rs1 = 0.0f;
        float* pr0 = Ps + (wm + lr) * 68;
        float* pr1 = Ps + (wm + lr + 8) * 68;
#pragma unroll
        for (int nf = 0; nf < 8; nf++) {
            float p0 = __expf(sf[nf][0] - mn0);
            float p1 = __expf(sf[nf][1] - mn0);
            float p2 = __expf(sf[nf][2] - mn1);
            float p3 = __expf(sf[nf][3] - mn1);
            rs0 += p0 + p1;
            rs1 += p2 + p3;
            *(float2*)(pr0 + nf * 8 + 2 * lc) = make_float2(p0, p1);
            *(float2*)(pr1 + nf * 8 + 2 * lc) = make_float2(p2, p3);
        }
        rs0 += __shfl_xor_sync(0xffffffffu, rs0, 1);
        rs0 += __shfl_xor_sync(0xffffffffu, rs0, 2);
        rs1 += __shfl_xor_sync(0xffffffffu, rs1, 1);
        rs1 += __shfl_xor_sync(0xffffffffu, rs1, 2);
        l0 = l0 * corr0 + rs0;
        l1 = l1 * corr1 + rs1;
        m0 = mn0; m1 = mn1;
#pragma unroll
        for (int nf = 0; nf < 8; nf++) {
            of[nf][0] *= corr0; of[nf][1] *= corr0;
            of[nf][2] *= corr1; of[nf][3] *= corr1;
        }
        __syncwarp();

#pragma unroll
        for (int ks = 0; ks < 8; ks++) {
            uint32_t af[4];
            const float* p = Ps + (wm + lr) * 68 + ks * 8 + lc;
            af[0] = __float_as_uint(p[0]);
            af[1] = __float_as_uint(p[8 * 68]);
            af[2] = __float_as_uint(p[4]);
            af[3] = __float_as_uint(p[8 * 68 + 4]);
#pragma unroll
            for (int nf = 0; nf < 8; nf++) {
                uint32_t bf2[2];
                const float* pv = Vs + (ks * 8 + lc) * 72 + nf * 8 + lr;
                bf2[0] = __float_as_uint(pv[0]);
                bf2[1] = __float_as_uint(pv[4 * 72]);
                mma_tf32(of[nf], af, bf2);
            }
        }
    }

    const float inv0 = 1.0f / l0;
    const float inv1 = 1.0f / l1;
#pragma unroll
    for (int nf = 0; nf < 8; nf++) {
        int col = nf * 8 + 2 * lc;
        *(float2*)(Og + base + (size_t)r0g * DMODEL + col) =
            make_float2(of[nf][0] * inv0, of[nf][1] * inv0);
        *(float2*)(Og + base + (size_t)r1g * DMODEL + col) =
            make_float2(of[nf][2] * inv1, of[nf][3] * inv1);
    }
}

// ---------------------------------------------------------------------------
extern "C" void kernel_launch(void* const* d_in, const int* in_sizes, int n_in,
                              void* d_out, int out_size) {
    const float* x   = (const float*)d_in[0];
    const float* qW1 = (const float*)d_in[1];
    const float* qb1 = (const float*)d_in[2];
    const float* qW2 = (const float*)d_in[3];
    const float* qb2 = (const float*)d_in[4];
    const float* kW1 = (const float*)d_in[5];
    const float* kb1 = (const float*)d_in[6];
    const float* kW2 = (const float*)d_in[7];
    const float* kb2 = (const float*)d_in[8];
    const float* vW1 = (const float*)d_in[9];
    const float* vb1 = (const float*)d_in[10];
    const float* vW2 = (const float*)d_in[11];
    const float* vb2 = (const float*)d_in[12];

    float* out = (float*)d_out;
    const size_t seg = (size_t)MROWS * DMODEL;
    float* k_out = out;
    float* v_out = out + seg;
    float* o_out = out + 2 * seg;

    __half* ghh = nullptr; __half* gxh = nullptr;
    __half* gw1t = nullptr; __half* gw2t = nullptr;
    float* gq = nullptr;
    cudaGetSymbolAddress((void**)&ghh, g_hh);
    cudaGetSymbolAddress((void**)&gxh, g_xh);
    cudaGetSymbolAddress((void**)&gw1t, g_w1t);
    cudaGetSymbolAddress((void**)&gw2t, g_w2t);
    cudaGetSymbolAddress((void**)&gq, g_q);
    __half* gh0 = ghh;
    __half* gh1 = ghh + (size_t)MROWS * HID;
    __half* gh2 = ghh + 2 * (size_t)MROWS * HID;
    __half* w1t0 = gw1t;
    __half* w1t1 = gw1t + (size_t)HID * DMODEL;
    __half* w1t2 = gw1t + 2 * (size_t)HID * DMODEL;
    __half* w2t0 = gw2t;
    __half* w2t1 = gw2t + (size_t)DMODEL * HID;
    __half* w2t2 = gw2t + 2 * (size_t)DMODEL * HID;

    cudaFuncSetAttribute(gemm_mma, cudaFuncAttributeMaxDynamicSharedMemorySize, SM_BYTES);
    cudaFuncSetAttribute(attention_mma, cudaFuncAttributeMaxDynamicSharedMemorySize, ATT_SMEM_BYTES);

    // Prepass: convert x to fp16; transpose+convert weights to fp16
    {
        int n4 = (MROWS * DMODEL) / 4;
        cvt_x_kernel<<<(n4 + 255) / 256, 256>>>(x, gxh, n4);
        dim3 tb(32, 8);
        transpose_h<<<dim3(HID / 32, DMODEL / 32, 3), tb>>>(qW1, kW1, vW1, w1t0, w1t1, w1t2, DMODEL, HID);
        transpose_h<<<dim3(DMODEL / 32, HID / 32, 3), tb>>>(qW2, kW2, vW2, w2t0, w2t1, w2t2, HID, DMODEL);
    }

    // Stage 1: hidden[z] = fp16(gelu(x @ W1[z] + b1[z]))   mode=2 all
    {
        dim3 g(HID / BN, MROWS / BM, 3);
        gemm_mma<<<g, 256, SM_BYTES>>>(gxh, gxh, gxh,
                                       w1t0, w1t1, w1t2,
                                       qb1, kb1, vb1,
                                       gh0, gh1, gh2,
                                       HID, DMODEL, (2) | (2 << 2) | (2 << 4));
    }
    // Stage 2: q = h0@qW2+qb2 ; k = h1@kW2+kb2 ; v = gelu(h2@vW2+vb2)  (fp32 out)
    {
        dim3 g(DMODEL / BN, MROWS / BM, 3);
        gemm_mma<<<g, 256, SM_BYTES>>>(gh0, gh1, gh2,
                                       w2t0, w2t1, w2t2,
                                       qb2, kb2, vb2,
                                       gq, k_out, v_out,
                                       DMODEL, HID, (0) | (0 << 2) | (1 << 4));
    }
    // Stage 3: attention (tf32 tensor cores, pipelined)
    {
        dim3 ga(SEQ / 128, 2 * NHEADS);
        attention_mma<<<ga, 256, ATT_SMEM_BYTES>>>(gq, k_out, v_out, o_out);
    }
}

// round 10
// speedup vs baseline: 5.3678x; 1.1975x over previous
#include <cuda_runtime.h>
#include <cuda_fp16.h>
#include <math.h>
#include <stdint.h>

// ---------------------------------------------------------------------------
// Problem: x (2,2048,512); W1 (512,2048); W2 (2048,512); HEADS=8
// M = 4096 rows. Output = concat(k, v, out), each 4096*512 fp32.
// R10: GEMMs fp16 m16n8k16 (as R9). Attention now ALSO fp16 m16n8k16 with
// register-resident P (C-fragment -> A-fragment direct conversion).
// ---------------------------------------------------------------------------
#define MROWS 4096
#define DMODEL 512
#define HID 2048
#define SEQ 2048
#define NHEADS 8
#define DHEAD 64

#define BM 128
#define BN 128
#define BKK 32
#define HSTRIDE 40      // gemm smem row stride in halves

// Scratch (device globals: allocation-free rule)
__device__ __align__(16) __half g_hh[3][(size_t)MROWS * HID];     // hidden fp16
__device__ __align__(16) __half g_xh[(size_t)MROWS * DMODEL];     // x fp16
__device__ __align__(16) __half g_w1t[3][(size_t)HID * DMODEL];
__device__ __align__(16) __half g_w2t[3][(size_t)DMODEL * HID];
__device__ __align__(16) __half g_qh[(size_t)MROWS * DMODEL];     // q*0.125 fp16
__device__ __align__(16) __half g_kh[(size_t)MROWS * DMODEL];     // k fp16 copy
__device__ __align__(16) __half g_vh[(size_t)MROWS * DMODEL];     // v fp16 copy

// ----------------------------- helpers -------------------------------------
__device__ __forceinline__ uint32_t smem_u32(const void* p) {
    uint32_t a;
    asm("{ .reg .u64 t; cvta.to.shared.u64 t, %1; cvt.u32.u64 %0, t; }" : "=r"(a) : "l"(p));
    return a;
}
__device__ __forceinline__ void cp16(uint32_t saddr, const void* g) {
    asm volatile("cp.async.cg.shared.global [%0], [%1], 16;" :: "r"(saddr), "l"(g));
}
__device__ __forceinline__ float gelu_f(float x) {
    float x3 = x * x * x;
    float t = tanhf(0.7978845608028654f * (x + 0.044715f * x3));
    return 0.5f * x * (1.0f + t);
}
__device__ __forceinline__ void mma_f16(float* c, const uint32_t* a, const uint32_t* b) {
    asm volatile(
        "mma.sync.aligned.m16n8k16.row.col.f32.f16.f16.f32 "
        "{%0,%1,%2,%3}, {%4,%5,%6,%7}, {%8,%9}, {%0,%1,%2,%3};"
        : "+f"(c[0]), "+f"(c[1]), "+f"(c[2]), "+f"(c[3])
        : "r"(a[0]), "r"(a[1]), "r"(a[2]), "r"(a[3]), "r"(b[0]), "r"(b[1]));
}
__device__ __forceinline__ void ldsm4(uint32_t* r, uint32_t addr) {
    asm volatile("ldmatrix.sync.aligned.m8n8.x4.shared.b16 {%0,%1,%2,%3}, [%4];"
        : "=r"(r[0]), "=r"(r[1]), "=r"(r[2]), "=r"(r[3]) : "r"(addr));
}
__device__ __forceinline__ void ldsm4t(uint32_t* r, uint32_t addr) {
    asm volatile("ldmatrix.sync.aligned.m8n8.x4.trans.shared.b16 {%0,%1,%2,%3}, [%4];"
        : "=r"(r[0]), "=r"(r[1]), "=r"(r[2]), "=r"(r[3]) : "r"(addr));
}
__device__ __forceinline__ uint32_t h2pack(float a, float b) {
    __half2 h = __floats2half2_rn(a, b);
    return *(uint32_t*)&h;
}

// ---------------------------------------------------------------------------
// Prepass: convert x to fp16
// ---------------------------------------------------------------------------
__global__ void cvt_x_kernel(const float* __restrict__ in, __half* __restrict__ out, int n4) {
    int i = blockIdx.x * blockDim.x + threadIdx.x;
    if (i < n4) {
        float4 v = ((const float4*)in)[i];
        __half2 h0 = __floats2half2_rn(v.x, v.y);
        __half2 h1 = __floats2half2_rn(v.z, v.w);
        ((uint2*)out)[i] = make_uint2(*(uint32_t*)&h0, *(uint32_t*)&h1);
    }
}

// ---------------------------------------------------------------------------
// Prepass: transpose weights to fp16. src R x C fp32 -> dst C x R fp16.
// ---------------------------------------------------------------------------
__global__ void transpose_h(const float* __restrict__ s0, const float* __restrict__ s1,
                            const float* __restrict__ s2,
                            __half* __restrict__ d0, __half* __restrict__ d1,
                            __half* __restrict__ d2, int R, int C) {
    __shared__ float tile[32][33];
    const int z = blockIdx.z;
    const float* src = (z == 0) ? s0 : (z == 1) ? s1 : s2;
    __half* dst = (z == 0) ? d0 : (z == 1) ? d1 : d2;
    int tx = threadIdx.x, ty = threadIdx.y;
    int bx = blockIdx.x, by = blockIdx.y;
#pragma unroll
    for (int j = 0; j < 4; j++) {
        int r = by * 32 + ty + j * 8;
        int c = bx * 32 + tx;
        tile[ty + j * 8][tx] = src[(size_t)r * C + c];
    }
    __syncthreads();
#pragma unroll
    for (int j = 0; j < 4; j++) {
        int dr = bx * 32 + ty + j * 8;
        int dc = by * 32 + tx;
        dst[(size_t)dr * R + dc] = __float2half_rn(tile[tx][ty + j * 8]);
    }
}

// ---------------------------------------------------------------------------
// fp16 tensor-core GEMM: out = act(A[z] @ Bt[z]^T + b[z])
// mode per z (4 bits): bit0 gelu, bit1 write fp32 to C, bit2 write fp16 to
// C16, bit3 scale result by 0.125 (for q).
// ---------------------------------------------------------------------------
#define GA_OFF(buf) ((buf) * 10240u)
#define GB_OFF(buf) (20480u + (buf) * 10240u)
#define SM_BYTES 40960

__global__ void __launch_bounds__(256, 2) gemm_mma(
    const __half* __restrict__ A0, const __half* __restrict__ A1, const __half* __restrict__ A2,
    const __half* __restrict__ B0, const __half* __restrict__ B1, const __half* __restrict__ B2,
    const float* __restrict__ bias0, const float* __restrict__ bias1, const float* __restrict__ bias2,
    float* __restrict__ C0, float* __restrict__ C1, float* __restrict__ C2,
    __half* __restrict__ H0, __half* __restrict__ H1, __half* __restrict__ H2,
    int N, int K, int actModes)
{
    extern __shared__ char smem[];
    const uint32_t sb = smem_u32(smem);

    const int z = blockIdx.z;
    const __half* A = (z == 0) ? A0 : (z == 1) ? A1 : A2;
    const __half* B = (z == 0) ? B0 : (z == 1) ? B1 : B2;
    const float* bias = (z == 0) ? bias0 : (z == 1) ? bias1 : bias2;
    float* C = (z == 0) ? C0 : (z == 1) ? C1 : C2;
    __half* H = (z == 0) ? H0 : (z == 1) ? H1 : H2;
    const int mode = (actModes >> (4 * z)) & 15;

    const int tid = threadIdx.x;
    const int wid = tid >> 5;
    const int lane = tid & 31;
    const int bm = blockIdx.y * BM;
    const int bn = blockIdx.x * BN;
    const int wm = (wid >> 2) * 64;
    const int wn = (wid & 3) * 32;

    const int lr = lane >> 2;
    const int lc = lane & 3;

    const int grow = tid >> 2;
    const int gchunk = tid & 3;

    uint32_t aOff[4];
#pragma unroll
    for (int mt = 0; mt < 4; mt++)
        aOff[mt] = (uint32_t)(wm + mt * 16 + (lane & 15)) * (HSTRIDE * 2) + ((lane >> 4) << 4);
    uint32_t bOff[2];
#pragma unroll
    for (int j = 0; j < 2; j++)
        bOff[j] = (uint32_t)(wn + (2 * j + (lane >> 4)) * 8 + (lane & 7)) * (HSTRIDE * 2) + (((lane >> 3) & 1) << 4);

    float acc[4][4][4];
#pragma unroll
    for (int i = 0; i < 4; i++)
#pragma unroll
        for (int j = 0; j < 4; j++)
#pragma unroll
            for (int t = 0; t < 4; t++) acc[i][j][t] = 0.0f;

    auto loadTile = [&](int kc, int buf) {
#pragma unroll
        for (int j = 0; j < 2; j++) {
            int r = grow + 64 * j;
            cp16(sb + GA_OFF(buf) + (uint32_t)r * (HSTRIDE * 2) + gchunk * 16,
                 A + (size_t)(bm + r) * K + kc * BKK + gchunk * 8);
            cp16(sb + GB_OFF(buf) + (uint32_t)r * (HSTRIDE * 2) + gchunk * 16,
                 B + (size_t)(bn + r) * K + kc * BKK + gchunk * 8);
        }
        asm volatile("cp.async.commit_group;" ::: "memory");
    };

    const int NC = K / BKK;
    loadTile(0, 0);

    for (int c = 0; c < NC; c++) {
        const int b = c & 1;
        __syncthreads();
        if (c + 1 < NC) {
            loadTile(c + 1, b ^ 1);
            asm volatile("cp.async.wait_group 1;" ::: "memory");
        } else {
            asm volatile("cp.async.wait_group 0;" ::: "memory");
        }
        __syncthreads();

        const uint32_t sA = sb + GA_OFF(b);
        const uint32_t sB = sb + GB_OFF(b);
#pragma unroll
        for (int kk = 0; kk < 2; kk++) {
            const uint32_t kb = kk * 32;
            uint32_t af[4][4], bf[4][2];
#pragma unroll
            for (int mt = 0; mt < 4; mt++)
                ldsm4(af[mt], sA + aOff[mt] + kb);
#pragma unroll
            for (int j = 0; j < 2; j++) {
                uint32_t r[4];
                ldsm4(r, sB + bOff[j] + kb);
                bf[2 * j][0] = r[0]; bf[2 * j][1] = r[1];
                bf[2 * j + 1][0] = r[2]; bf[2 * j + 1][1] = r[3];
            }
#pragma unroll
            for (int mt = 0; mt < 4; mt++)
#pragma unroll
                for (int nt = 0; nt < 4; nt++)
                    mma_f16(acc[mt][nt], af[mt], bf[nt]);
        }
    }

    const float scl = (mode & 8) ? 0.125f : 1.0f;
    float2 bv[4];
#pragma unroll
    for (int nt = 0; nt < 4; nt++) {
        int col = bn + wn + nt * 8 + 2 * lc;
        bv[nt] = *(const float2*)(bias + col);
    }
#pragma unroll
    for (int mt = 0; mt < 4; mt++) {
        int row0 = bm + wm + mt * 16 + lr;
#pragma unroll
        for (int nt = 0; nt < 4; nt++) {
            int col = bn + wn + nt * 8 + 2 * lc;
#pragma unroll
            for (int half = 0; half < 2; half++) {
                int row = row0 + half * 8;
                float v0 = acc[mt][nt][2 * half + 0] + bv[nt].x;
                float v1 = acc[mt][nt][2 * half + 1] + bv[nt].y;
                if (mode & 1) { v0 = gelu_f(v0); v1 = gelu_f(v1); }
                v0 *= scl; v1 *= scl;
                if (mode & 2)
                    *(float2*)(C + (size_t)row * N + col) = make_float2(v0, v1);
                if (mode & 4) {
                    __half2 h = __floats2half2_rn(v0, v1);
                    *(__half2*)(H + (size_t)row * N + col) = h;
                }
            }
        }
    }
}

// ---------------------------------------------------------------------------
// fp16 tensor-core causal flash attention, register-resident P.
// CTA: 128 query rows x one (batch,head); 8 warps x 16 rows; 64-key tiles.
// Q (pre-scaled fp16), K, V all fp16 in smem, row stride 72 halves (144B:
// ldmatrix conflict-free). S and O accumulate fp32. P: C-fragment -> A-
// fragment via __floats2half2_rn, never touches smem.
// Smem (halves): Q[128*72] | K[2][64*72] | V[2][64*72] = 27648 (54KB).
// ---------------------------------------------------------------------------
#define AQH 0
#define AKH 9216
#define AVH 18432
#define AKVBUF 4608
#define ATTH_BYTES (27648 * 2)

__global__ void __launch_bounds__(256, 2) attention_h(
    const __half* __restrict__ Qg, const __half* __restrict__ Kg,
    const __half* __restrict__ Vg, float* __restrict__ Og)
{
    extern __shared__ __half smh[];
    const uint32_t sb = smem_u32(smh);

    const int tid = threadIdx.x;
    const int wid = tid >> 5;
    const int lane = tid & 31;
    const int lr = lane >> 2;
    const int lc = lane & 3;
    const int qt = gridDim.x - 1 - blockIdx.x;   // heavy tiles first
    const int nb = blockIdx.y >> 3;
    const int h  = blockIdx.y & 7;
    const int bm = qt * 128;
    const int wm = wid * 16;

    const size_t base = ((size_t)nb * SEQ) * DMODEL + (size_t)h * DHEAD;

    // Q staging: 128 rows x 8 16B-chunks = 1024 chunks, 4/thread. Group 0.
#pragma unroll
    for (int j = 0; j < 4; j++) {
        int c = tid + 256 * j;
        int r = c >> 3;
        int ch = c & 7;
        cp16(sb + (AQH + r * 72 + ch * 8) * 2, Qg + base + (size_t)(bm + r) * DMODEL + ch * 8);
    }
    asm volatile("cp.async.commit_group;" ::: "memory");

    auto loadKV = [&](int kt, int b) {
#pragma unroll
        for (int j = 0; j < 2; j++) {
            int c = tid + 256 * j;
            int r = c >> 3;
            int ch = c & 7;
            size_t g = base + (size_t)(kt * 64 + r) * DMODEL + ch * 8;
            cp16(sb + (AKH + b * AKVBUF + r * 72 + ch * 8) * 2, Kg + g);
            cp16(sb + (AVH + b * AKVBUF + r * 72 + ch * 8) * 2, Vg + g);
        }
        asm volatile("cp.async.commit_group;" ::: "memory");
    };

    loadKV(0, 0);   // group 1

    // Wait for Q (group 0), load Q fragments.
    asm volatile("cp.async.wait_group 1;" ::: "memory");
    __syncthreads();
    uint32_t qf[4][4];
    {
        uint32_t qOff = sb + (AQH + (uint32_t)(wm + (lane & 15)) * 72) * 2 + ((lane >> 4) << 4);
#pragma unroll
        for (int ks = 0; ks < 4; ks++)
            ldsm4(qf[ks], qOff + ks * 32);
    }

    // Per-lane ldmatrix offsets (halves, relative to K/V buffer base).
    uint32_t kOff[4];   // S: B-fragments, non-trans; j covers key tiles 2j,2j+1
#pragma unroll
    for (int j = 0; j < 4; j++)
        kOff[j] = (uint32_t)((2 * j + (lane >> 4)) * 8 + (lane & 7)) * 72 + (((lane >> 3) & 1) << 3);
    uint32_t vOff[4];   // PV: B-fragments, trans; j covers dim tiles 2j,2j+1
#pragma unroll
    for (int j = 0; j < 4; j++)
        vOff[j] = (uint32_t)((((lane >> 3) & 1) << 3) + (lane & 7)) * 72 + 16 * j + ((lane >> 4) << 3);

    float of[8][4];
#pragma unroll
    for (int nf = 0; nf < 8; nf++)
#pragma unroll
        for (int t = 0; t < 4; t++) of[nf][t] = 0.0f;
    float m0 = -1e30f, m1 = -1e30f, l0 = 0.0f, l1 = 0.0f;

    const int r0g = bm + wm + lr;
    const int r1g = r0g + 8;
    const int ntiles = qt * 2 + 2;

    for (int kt = 0; kt < ntiles; kt++) {
        const int b = kt & 1;
        asm volatile("cp.async.wait_group 0;" ::: "memory");
        __syncthreads();
        if (kt + 1 < ntiles) loadKV(kt + 1, b ^ 1);

        const uint32_t sK = sb + (AKH + b * AKVBUF) * 2;
        const uint32_t sV = sb + (AVH + b * AKVBUF) * 2;

        // S = Q K^T
        float sf[8][4];
#pragma unroll
        for (int nf = 0; nf < 8; nf++)
#pragma unroll
            for (int t = 0; t < 4; t++) sf[nf][t] = 0.0f;
#pragma unroll
        for (int ks = 0; ks < 4; ks++) {
            uint32_t bf[8][2];
#pragma unroll
            for (int j = 0; j < 4; j++) {
                uint32_t r[4];
                ldsm4(r, sK + kOff[j] * 2 + ks * 32);
                bf[2 * j][0] = r[0]; bf[2 * j][1] = r[1];
                bf[2 * j + 1][0] = r[2]; bf[2 * j + 1][1] = r[3];
            }
#pragma unroll
            for (int nf = 0; nf < 8; nf++)
                mma_f16(sf[nf], qf[ks], bf[nf]);
        }

        // Causal mask (only last two tiles touch the diagonal)
        if (kt >= ntiles - 2) {
#pragma unroll
            for (int nf = 0; nf < 8; nf++) {
                int c0 = kt * 64 + nf * 8 + 2 * lc;
                if (c0     > r0g) sf[nf][0] = -1e30f;
                if (c0 + 1 > r0g) sf[nf][1] = -1e30f;
                if (c0     > r1g) sf[nf][2] = -1e30f;
                if (c0 + 1 > r1g) sf[nf][3] = -1e30f;
            }
        }

        // Online softmax (quad shuffles), P packed straight into A-fragments.
        float mx0 = -1e30f, mx1 = -1e30f;
#pragma unroll
        for (int nf = 0; nf < 8; nf++) {
            mx0 = fmaxf(mx0, fmaxf(sf[nf][0], sf[nf][1]));
            mx1 = fmaxf(mx1, fmaxf(sf[nf][2], sf[nf][3]));
        }
        mx0 = fmaxf(mx0, __shfl_xor_sync(0xffffffffu, mx0, 1));
        mx0 = fmaxf(mx0, __shfl_xor_sync(0xffffffffu, mx0, 2));
        mx1 = fmaxf(mx1, __shfl_xor_sync(0xffffffffu, mx1, 1));
        mx1 = fmaxf(mx1, __shfl_xor_sync(0xffffffffu, mx1, 2));
        float mn0 = fmaxf(m0, mx0), mn1 = fmaxf(m1, mx1);
        float corr0 = __expf(m0 - mn0), corr1 = __expf(m1 - mn1);

        float rs0 = 0.0f, rs1 = 0.0f;
        uint32_t pa[4][4];
#pragma unroll
        for (int nf = 0; nf < 8; nf++) {
            float p0 = __expf(sf[nf][0] - mn0);
            float p1 = __expf(sf[nf][1] - mn0);
            float p2 = __expf(sf[nf][2] - mn1);
            float p3 = __expf(sf[nf][3] - mn1);
            rs0 += p0 + p1;
            rs1 += p2 + p3;
            // A-fragment for PV kstep ks = nf/2: regs {0,1} from even nf, {2,3} odd.
            int ks = nf >> 1;
            int hi = (nf & 1) << 1;
            pa[ks][hi + 0] = h2pack(p0, p1);
            pa[ks][hi + 1] = h2pack(p2, p3);
        }
        rs0 += __shfl_xor_sync(0xffffffffu, rs0, 1);
        rs0 += __shfl_xor_sync(0xffffffffu, rs0, 2);
        rs1 += __shfl_xor_sync(0xffffffffu, rs1, 1);
        rs1 += __shfl_xor_sync(0xffffffffu, rs1, 2);
        l0 = l0 * corr0 + rs0;
        l1 = l1 * corr1 + rs1;
        m0 = mn0; m1 = mn1;
#pragma unroll
        for (int nf = 0; nf < 8; nf++) {
            of[nf][0] *= corr0; of[nf][1] *= corr0;
            of[nf][2] *= corr1; of[nf][3] *= corr1;
        }

        // O += P V  (V via ldmatrix.trans: B-fragments with k = key rows)
#pragma unroll
        for (int ks = 0; ks < 4; ks++) {
            uint32_t bf[8][2];
#pragma unroll
            for (int j = 0; j < 4; j++) {
                uint32_t r[4];
                ldsm4t(r, sV + (vOff[j] + (uint32_t)ks * 16 * 72) * 2);
                bf[2 * j][0] = r[0]; bf[2 * j][1] = r[1];
                bf[2 * j + 1][0] = r[2]; bf[2 * j + 1][1] = r[3];
            }
#pragma unroll
            for (int nf = 0; nf < 8; nf++)
                mma_f16(of[nf], pa[ks], bf[nf]);
        }
    }

    const float inv0 = 1.0f / l0;
    const float inv1 = 1.0f / l1;
#pragma unroll
    for (int nf = 0; nf < 8; nf++) {
        int col = nf * 8 + 2 * lc;
        *(float2*)(Og + base + (size_t)r0g * DMODEL + col) =
            make_float2(of[nf][0] * inv0, of[nf][1] * inv0);
        *(float2*)(Og + base + (size_t)r1g * DMODEL + col) =
            make_float2(of[nf][2] * inv1, of[nf][3] * inv1);
    }
}

// ---------------------------------------------------------------------------
extern "C" void kernel_launch(void* const* d_in, const int* in_sizes, int n_in,
                              void* d_out, int out_size) {
    const float* x   = (const float*)d_in[0];
    const float* qW1 = (const float*)d_in[1];
    const float* qb1 = (const float*)d_in[2];
    const float* qW2 = (const float*)d_in[3];
    const float* qb2 = (const float*)d_in[4];
    const float* kW1 = (const float*)d_in[5];
    const float* kb1 = (const float*)d_in[6];
    const float* kW2 = (const float*)d_in[7];
    const float* kb2 = (const float*)d_in[8];
    const float* vW1 = (const float*)d_in[9];
    const float* vb1 = (const float*)d_in[10];
    const float* vW2 = (const float*)d_in[11];
    const float* vb2 = (const float*)d_in[12];

    float* out = (float*)d_out;
    const size_t seg = (size_t)MROWS * DMODEL;
    float* k_out = out;
    float* v_out = out + seg;
    float* o_out = out + 2 * seg;

    __half *ghh, *gxh, *gw1t, *gw2t, *gqh, *gkh, *gvh;
    cudaGetSymbolAddress((void**)&ghh, g_hh);
    cudaGetSymbolAddress((void**)&gxh, g_xh);
    cudaGetSymbolAddress((void**)&gw1t, g_w1t);
    cudaGetSymbolAddress((void**)&gw2t, g_w2t);
    cudaGetSymbolAddress((void**)&gqh, g_qh);
    cudaGetSymbolAddress((void**)&gkh, g_kh);
    cudaGetSymbolAddress((void**)&gvh, g_vh);
    __half* gh0 = ghh;
    __half* gh1 = ghh + (size_t)MROWS * HID;
    __half* gh2 = ghh + 2 * (size_t)MROWS * HID;
    __half* w1t0 = gw1t;
    __half* w1t1 = gw1t + (size_t)HID * DMODEL;
    __half* w1t2 = gw1t + 2 * (size_t)HID * DMODEL;
    __half* w2t0 = gw2t;
    __half* w2t1 = gw2t + (size_t)DMODEL * HID;
    __half* w2t2 = gw2t + 2 * (size_t)DMODEL * HID;

    cudaFuncSetAttribute(gemm_mma, cudaFuncAttributeMaxDynamicSharedMemorySize, SM_BYTES);
    cudaFuncSetAttribute(attention_h, cudaFuncAttributeMaxDynamicSharedMemorySize, ATTH_BYTES);

    // Prepass
    {
        int n4 = (MROWS * DMODEL) / 4;
        cvt_x_kernel<<<(n4 + 255) / 256, 256>>>(x, gxh, n4);
        dim3 tb(32, 8);
        transpose_h<<<dim3(HID / 32, DMODEL / 32, 3), tb>>>(qW1, kW1, vW1, w1t0, w1t1, w1t2, DMODEL, HID);
        transpose_h<<<dim3(DMODEL / 32, HID / 32, 3), tb>>>(qW2, kW2, vW2, w2t0, w2t1, w2t2, HID, DMODEL);
    }

    // Stage 1: hidden[z] = fp16(gelu(x @ W1[z] + b1[z]))  — mode 5 (gelu|fp16)
    {
        dim3 g(HID / BN, MROWS / BM, 3);
        gemm_mma<<<g, 256, SM_BYTES>>>(gxh, gxh, gxh,
                                       w1t0, w1t1, w1t2,
                                       qb1, kb1, vb1,
                                       nullptr, nullptr, nullptr,
                                       gh0, gh1, gh2,
                                       HID, DMODEL, (5) | (5 << 4) | (5 << 8));
    }
    // Stage 2: q: fp16*0.125 (mode 12); k: fp32+fp16 (mode 6); v: gelu fp32+fp16 (mode 7)
    {
        dim3 g(DMODEL / BN, MROWS / BM, 3);
        gemm_mma<<<g, 256, SM_BYTES>>>(gh0, gh1, gh2,
                                       w2t0, w2t1, w2t2,
                                       qb2, kb2, vb2,
                                       nullptr, k_out, v_out,
                                       gqh, gkh, gvh,
                                       DMODEL, HID, (12) | (6 << 4) | (7 << 8));
    }
    // Stage 3: attention (fp16 tensor cores, register-resident P)
    {
        dim3 ga(SEQ / 128, 2 * NHEADS);
        attention_h<<<ga, 256, ATTH_BYTES>>>(gqh, gkh, gvh, o_out);
    }
}

// round 11
// speedup vs baseline: 5.5970x; 1.0427x over previous
#include <cuda_runtime.h>
#include <cuda_fp16.h>
#include <math.h>
#include <stdint.h>

// ---------------------------------------------------------------------------
// Problem: x (2,2048,512); W1 (512,2048); W2 (2048,512); HEADS=8
// M = 4096 rows. Output = concat(k, v, out), each 4096*512 fp32.
// R11: GEMM mainloop -> 4-stage cp.async ring, ONE __syncthreads per chunk.
// Attention (fp16, register-resident P) unchanged from R10.
// ---------------------------------------------------------------------------
#define MROWS 4096
#define DMODEL 512
#define HID 2048
#define SEQ 2048
#define NHEADS 8
#define DHEAD 64

#define BM 128
#define BN 128
#define BKK 32
#define HSTRIDE 40      // gemm smem row stride in halves

// Scratch (device globals: allocation-free rule)
__device__ __align__(16) __half g_hh[3][(size_t)MROWS * HID];     // hidden fp16
__device__ __align__(16) __half g_xh[(size_t)MROWS * DMODEL];     // x fp16
__device__ __align__(16) __half g_w1t[3][(size_t)HID * DMODEL];
__device__ __align__(16) __half g_w2t[3][(size_t)DMODEL * HID];
__device__ __align__(16) __half g_qh[(size_t)MROWS * DMODEL];     // q*0.125 fp16
__device__ __align__(16) __half g_kh[(size_t)MROWS * DMODEL];     // k fp16 copy
__device__ __align__(16) __half g_vh[(size_t)MROWS * DMODEL];     // v fp16 copy

// ----------------------------- helpers -------------------------------------
__device__ __forceinline__ uint32_t smem_u32(const void* p) {
    uint32_t a;
    asm("{ .reg .u64 t; cvta.to.shared.u64 t, %1; cvt.u32.u64 %0, t; }" : "=r"(a) : "l"(p));
    return a;
}
__device__ __forceinline__ void cp16(uint32_t saddr, const void* g) {
    asm volatile("cp.async.cg.shared.global [%0], [%1], 16;" :: "r"(saddr), "l"(g));
}
__device__ __forceinline__ float gelu_f(float x) {
    float x3 = x * x * x;
    float t = tanhf(0.7978845608028654f * (x + 0.044715f * x3));
    return 0.5f * x * (1.0f + t);
}
__device__ __forceinline__ void mma_f16(float* c, const uint32_t* a, const uint32_t* b) {
    asm volatile(
        "mma.sync.aligned.m16n8k16.row.col.f32.f16.f16.f32 "
        "{%0,%1,%2,%3}, {%4,%5,%6,%7}, {%8,%9}, {%0,%1,%2,%3};"
        : "+f"(c[0]), "+f"(c[1]), "+f"(c[2]), "+f"(c[3])
        : "r"(a[0]), "r"(a[1]), "r"(a[2]), "r"(a[3]), "r"(b[0]), "r"(b[1]));
}
__device__ __forceinline__ void ldsm4(uint32_t* r, uint32_t addr) {
    asm volatile("ldmatrix.sync.aligned.m8n8.x4.shared.b16 {%0,%1,%2,%3}, [%4];"
        : "=r"(r[0]), "=r"(r[1]), "=r"(r[2]), "=r"(r[3]) : "r"(addr));
}
__device__ __forceinline__ void ldsm4t(uint32_t* r, uint32_t addr) {
    asm volatile("ldmatrix.sync.aligned.m8n8.x4.trans.shared.b16 {%0,%1,%2,%3}, [%4];"
        : "=r"(r[0]), "=r"(r[1]), "=r"(r[2]), "=r"(r[3]) : "r"(addr));
}
__device__ __forceinline__ uint32_t h2pack(float a, float b) {
    __half2 h = __floats2half2_rn(a, b);
    return *(uint32_t*)&h;
}

// ---------------------------------------------------------------------------
// Prepass: convert x to fp16
// ---------------------------------------------------------------------------
__global__ void cvt_x_kernel(const float* __restrict__ in, __half* __restrict__ out, int n4) {
    int i = blockIdx.x * blockDim.x + threadIdx.x;
    if (i < n4) {
        float4 v = ((const float4*)in)[i];
        __half2 h0 = __floats2half2_rn(v.x, v.y);
        __half2 h1 = __floats2half2_rn(v.z, v.w);
        ((uint2*)out)[i] = make_uint2(*(uint32_t*)&h0, *(uint32_t*)&h1);
    }
}

// ---------------------------------------------------------------------------
// Prepass: transpose weights to fp16. src R x C fp32 -> dst C x R fp16.
// ---------------------------------------------------------------------------
__global__ void transpose_h(const float* __restrict__ s0, const float* __restrict__ s1,
                            const float* __restrict__ s2,
                            __half* __restrict__ d0, __half* __restrict__ d1,
                            __half* __restrict__ d2, int R, int C) {
    __shared__ float tile[32][33];
    const int z = blockIdx.z;
    const float* src = (z == 0) ? s0 : (z == 1) ? s1 : s2;
    __half* dst = (z == 0) ? d0 : (z == 1) ? d1 : d2;
    int tx = threadIdx.x, ty = threadIdx.y;
    int bx = blockIdx.x, by = blockIdx.y;
#pragma unroll
    for (int j = 0; j < 4; j++) {
        int r = by * 32 + ty + j * 8;
        int c = bx * 32 + tx;
        tile[ty + j * 8][tx] = src[(size_t)r * C + c];
    }
    __syncthreads();
#pragma unroll
    for (int j = 0; j < 4; j++) {
        int dr = bx * 32 + ty + j * 8;
        int dc = by * 32 + tx;
        dst[(size_t)dr * R + dc] = __float2half_rn(tile[tx][ty + j * 8]);
    }
}

// ---------------------------------------------------------------------------
// fp16 tensor-core GEMM, 4-stage ring: out = act(A[z] @ Bt[z]^T + b[z])
// mode per z (4 bits): bit0 gelu, bit1 fp32 out, bit2 fp16 out, bit3 *0.125.
// Smem: A[4][128*40h] | B[4][128*40h] = 80KB, 2 CTAs/SM.
// ---------------------------------------------------------------------------
#define GA_OFF(buf) ((buf) * 10240u)
#define GB_OFF(buf) (40960u + (buf) * 10240u)
#define SM_BYTES 81920

__global__ void __launch_bounds__(256, 2) gemm_mma(
    const __half* __restrict__ A0, const __half* __restrict__ A1, const __half* __restrict__ A2,
    const __half* __restrict__ B0, const __half* __restrict__ B1, const __half* __restrict__ B2,
    const float* __restrict__ bias0, const float* __restrict__ bias1, const float* __restrict__ bias2,
    float* __restrict__ C0, float* __restrict__ C1, float* __restrict__ C2,
    __half* __restrict__ H0, __half* __restrict__ H1, __half* __restrict__ H2,
    int N, int K, int actModes)
{
    extern __shared__ char smem[];
    const uint32_t sb = smem_u32(smem);

    const int z = blockIdx.z;
    const __half* A = (z == 0) ? A0 : (z == 1) ? A1 : A2;
    const __half* B = (z == 0) ? B0 : (z == 1) ? B1 : B2;
    const float* bias = (z == 0) ? bias0 : (z == 1) ? bias1 : bias2;
    float* C = (z == 0) ? C0 : (z == 1) ? C1 : C2;
    __half* H = (z == 0) ? H0 : (z == 1) ? H1 : H2;
    const int mode = (actModes >> (4 * z)) & 15;

    const int tid = threadIdx.x;
    const int wid = tid >> 5;
    const int lane = tid & 31;
    const int bm = blockIdx.y * BM;
    const int bn = blockIdx.x * BN;
    const int wm = (wid >> 2) * 64;
    const int wn = (wid & 3) * 32;

    const int lr = lane >> 2;
    const int lc = lane & 3;

    const int grow = tid >> 2;
    const int gchunk = tid & 3;

    uint32_t aOff[4];
#pragma unroll
    for (int mt = 0; mt < 4; mt++)
        aOff[mt] = (uint32_t)(wm + mt * 16 + (lane & 15)) * (HSTRIDE * 2) + ((lane >> 4) << 4);
    uint32_t bOff[2];
#pragma unroll
    for (int j = 0; j < 2; j++)
        bOff[j] = (uint32_t)(wn + (2 * j + (lane >> 4)) * 8 + (lane & 7)) * (HSTRIDE * 2) + (((lane >> 3) & 1) << 4);

    float acc[4][4][4];
#pragma unroll
    for (int i = 0; i < 4; i++)
#pragma unroll
        for (int j = 0; j < 4; j++)
#pragma unroll
            for (int t = 0; t < 4; t++) acc[i][j][t] = 0.0f;

    auto loadTile = [&](int kc, int buf) {
#pragma unroll
        for (int j = 0; j < 2; j++) {
            int r = grow + 64 * j;
            cp16(sb + GA_OFF(buf) + (uint32_t)r * (HSTRIDE * 2) + gchunk * 16,
                 A + (size_t)(bm + r) * K + kc * BKK + gchunk * 8);
            cp16(sb + GB_OFF(buf) + (uint32_t)r * (HSTRIDE * 2) + gchunk * 16,
                 B + (size_t)(bn + r) * K + kc * BKK + gchunk * 8);
        }
        asm volatile("cp.async.commit_group;" ::: "memory");
    };

    const int NC = K / BKK;
    // Prologue: 3 chunks in flight.
    loadTile(0, 0);
    loadTile(1, 1);
    loadTile(2, 2);

    for (int c = 0; c < NC; c++) {
        const int b = c & 3;
        asm volatile("cp.async.wait_group 2;" ::: "memory");  // chunk c ready
        __syncthreads();   // visibility + prev compute of buffer (c+3)&3 done
        if (c + 3 < NC) loadTile(c + 3, (c + 3) & 3);
        else asm volatile("cp.async.commit_group;" ::: "memory");  // keep count

        const uint32_t sA = sb + GA_OFF(b);
        const uint32_t sB = sb + GB_OFF(b);
#pragma unroll
        for (int kk = 0; kk < 2; kk++) {
            const uint32_t kb = kk * 32;
            uint32_t af[4][4], bf[4][2];
#pragma unroll
            for (int mt = 0; mt < 4; mt++)
                ldsm4(af[mt], sA + aOff[mt] + kb);
#pragma unroll
            for (int j = 0; j < 2; j++) {
                uint32_t r[4];
                ldsm4(r, sB + bOff[j] + kb);
                bf[2 * j][0] = r[0]; bf[2 * j][1] = r[1];
                bf[2 * j + 1][0] = r[2]; bf[2 * j + 1][1] = r[3];
            }
#pragma unroll
            for (int mt = 0; mt < 4; mt++)
#pragma unroll
                for (int nt = 0; nt < 4; nt++)
                    mma_f16(acc[mt][nt], af[mt], bf[nt]);
        }
    }

    const float scl = (mode & 8) ? 0.125f : 1.0f;
    float2 bv[4];
#pragma unroll
    for (int nt = 0; nt < 4; nt++) {
        int col = bn + wn + nt * 8 + 2 * lc;
        bv[nt] = *(const float2*)(bias + col);
    }
#pragma unroll
    for (int mt = 0; mt < 4; mt++) {
        int row0 = bm + wm + mt * 16 + lr;
#pragma unroll
        for (int nt = 0; nt < 4; nt++) {
            int col = bn + wn + nt * 8 + 2 * lc;
#pragma unroll
            for (int half = 0; half < 2; half++) {
                int row = row0 + half * 8;
                float v0 = acc[mt][nt][2 * half + 0] + bv[nt].x;
                float v1 = acc[mt][nt][2 * half + 1] + bv[nt].y;
                if (mode & 1) { v0 = gelu_f(v0); v1 = gelu_f(v1); }
                v0 *= scl; v1 *= scl;
                if (mode & 2)
                    *(float2*)(C + (size_t)row * N + col) = make_float2(v0, v1);
                if (mode & 4) {
                    __half2 h = __floats2half2_rn(v0, v1);
                    *(__half2*)(H + (size_t)row * N + col) = h;
                }
            }
        }
    }
}

// ---------------------------------------------------------------------------
// fp16 tensor-core causal flash attention, register-resident P (unchanged).
// ---------------------------------------------------------------------------
#define AQH 0
#define AKH 9216
#define AVH 18432
#define AKVBUF 4608
#define ATTH_BYTES (27648 * 2)

__global__ void __launch_bounds__(256, 2) attention_h(
    const __half* __restrict__ Qg, const __half* __restrict__ Kg,
    const __half* __restrict__ Vg, float* __restrict__ Og)
{
    extern __shared__ __half smh[];
    const uint32_t sb = smem_u32(smh);

    const int tid = threadIdx.x;
    const int wid = tid >> 5;
    const int lane = tid & 31;
    const int lr = lane >> 2;
    const int lc = lane & 3;
    const int qt = gridDim.x - 1 - blockIdx.x;
    const int nb = blockIdx.y >> 3;
    const int h  = blockIdx.y & 7;
    const int bm = qt * 128;
    const int wm = wid * 16;

    const size_t base = ((size_t)nb * SEQ) * DMODEL + (size_t)h * DHEAD;

#pragma unroll
    for (int j = 0; j < 4; j++) {
        int c = tid + 256 * j;
        int r = c >> 3;
        int ch = c & 7;
        cp16(sb + (AQH + r * 72 + ch * 8) * 2, Qg + base + (size_t)(bm + r) * DMODEL + ch * 8);
    }
    asm volatile("cp.async.commit_group;" ::: "memory");

    auto loadKV = [&](int kt, int b) {
#pragma unroll
        for (int j = 0; j < 2; j++) {
            int c = tid + 256 * j;
            int r = c >> 3;
            int ch = c & 7;
            size_t g = base + (size_t)(kt * 64 + r) * DMODEL + ch * 8;
            cp16(sb + (AKH + b * AKVBUF + r * 72 + ch * 8) * 2, Kg + g);
            cp16(sb + (AVH + b * AKVBUF + r * 72 + ch * 8) * 2, Vg + g);
        }
        asm volatile("cp.async.commit_group;" ::: "memory");
    };

    loadKV(0, 0);

    asm volatile("cp.async.wait_group 1;" ::: "memory");
    __syncthreads();
    uint32_t qf[4][4];
    {
        uint32_t qOff = sb + (AQH + (uint32_t)(wm + (lane & 15)) * 72) * 2 + ((lane >> 4) << 4);
#pragma unroll
        for (int ks = 0; ks < 4; ks++)
            ldsm4(qf[ks], qOff + ks * 32);
    }

    uint32_t kOff[4];
#pragma unroll
    for (int j = 0; j < 4; j++)
        kOff[j] = (uint32_t)((2 * j + (lane >> 4)) * 8 + (lane & 7)) * 72 + (((lane >> 3) & 1) << 3);
    uint32_t vOff[4];
#pragma unroll
    for (int j = 0; j < 4; j++)
        vOff[j] = (uint32_t)((((lane >> 3) & 1) << 3) + (lane & 7)) * 72 + 16 * j + ((lane >> 4) << 3);

    float of[8][4];
#pragma unroll
    for (int nf = 0; nf < 8; nf++)
#pragma unroll
        for (int t = 0; t < 4; t++) of[nf][t] = 0.0f;
    float m0 = -1e30f, m1 = -1e30f, l0 = 0.0f, l1 = 0.0f;

    const int r0g = bm + wm + lr;
    const int r1g = r0g + 8;
    const int ntiles = qt * 2 + 2;

    for (int kt = 0; kt < ntiles; kt++) {
        const int b = kt & 1;
        asm volatile("cp.async.wait_group 0;" ::: "memory");
        __syncthreads();
        if (kt + 1 < ntiles) loadKV(kt + 1, b ^ 1);

        const uint32_t sK = sb + (AKH + b * AKVBUF) * 2;
        const uint32_t sV = sb + (AVH + b * AKVBUF) * 2;

        float sf[8][4];
#pragma unroll
        for (int nf = 0; nf < 8; nf++)
#pragma unroll
            for (int t = 0; t < 4; t++) sf[nf][t] = 0.0f;
#pragma unroll
        for (int ks = 0; ks < 4; ks++) {
            uint32_t bf[8][2];
#pragma unroll
            for (int j = 0; j < 4; j++) {
                uint32_t r[4];
                ldsm4(r, sK + kOff[j] * 2 + ks * 32);
                bf[2 * j][0] = r[0]; bf[2 * j][1] = r[1];
                bf[2 * j + 1][0] = r[2]; bf[2 * j + 1][1] = r[3];
            }
#pragma unroll
            for (int nf = 0; nf < 8; nf++)
                mma_f16(sf[nf], qf[ks], bf[nf]);
        }

        if (kt >= ntiles - 2) {
#pragma unroll
            for (int nf = 0; nf < 8; nf++) {
                int c0 = kt * 64 + nf * 8 + 2 * lc;
                if (c0     > r0g) sf[nf][0] = -1e30f;
                if (c0 + 1 > r0g) sf[nf][1] = -1e30f;
                if (c0     > r1g) sf[nf][2] = -1e30f;
                if (c0 + 1 > r1g) sf[nf][3] = -1e30f;
            }
        }

        float mx0 = -1e30f, mx1 = -1e30f;
#pragma unroll
        for (int nf = 0; nf < 8; nf++) {
            mx0 = fmaxf(mx0, fmaxf(sf[nf][0], sf[nf][1]));
            mx1 = fmaxf(mx1, fmaxf(sf[nf][2], sf[nf][3]));
        }
        mx0 = fmaxf(mx0, __shfl_xor_sync(0xffffffffu, mx0, 1));
        mx0 = fmaxf(mx0, __shfl_xor_sync(0xffffffffu, mx0, 2));
        mx1 = fmaxf(mx1, __shfl_xor_sync(0xffffffffu, mx1, 1));
        mx1 = fmaxf(mx1, __shfl_xor_sync(0xffffffffu, mx1, 2));
        float mn0 = fmaxf(m0, mx0), mn1 = fmaxf(m1, mx1);
        float corr0 = __expf(m0 - mn0), corr1 = __expf(m1 - mn1);

        float rs0 = 0.0f, rs1 = 0.0f;
        uint32_t pa[4][4];
#pragma unroll
        for (int nf = 0; nf < 8; nf++) {
            float p0 = __expf(sf[nf][0] - mn0);
            float p1 = __expf(sf[nf][1] - mn0);
            float p2 = __expf(sf[nf][2] - mn1);
            float p3 = __expf(sf[nf][3] - mn1);
            rs0 += p0 + p1;
            rs1 += p2 + p3;
            int ks = nf >> 1;
            int hi = (nf & 1) << 1;
            pa[ks][hi + 0] = h2pack(p0, p1);
            pa[ks][hi + 1] = h2pack(p2, p3);
        }
        rs0 += __shfl_xor_sync(0xffffffffu, rs0, 1);
        rs0 += __shfl_xor_sync(0xffffffffu, rs0, 2);
        rs1 += __shfl_xor_sync(0xffffffffu, rs1, 1);
        rs1 += __shfl_xor_sync(0xffffffffu, rs1, 2);
        l0 = l0 * corr0 + rs0;
        l1 = l1 * corr1 + rs1;
        m0 = mn0; m1 = mn1;
#pragma unroll
        for (int nf = 0; nf < 8; nf++) {
            of[nf][0] *= corr0; of[nf][1] *= corr0;
            of[nf][2] *= corr1; of[nf][3] *= corr1;
        }

#pragma unroll
        for (int ks = 0; ks < 4; ks++) {
            uint32_t bf[8][2];
#pragma unroll
            for (int j = 0; j < 4; j++) {
                uint32_t r[4];
                ldsm4t(r, sV + (vOff[j] + (uint32_t)ks * 16 * 72) * 2);
                bf[2 * j][0] = r[0]; bf[2 * j][1] = r[1];
                bf[2 * j + 1][0] = r[2]; bf[2 * j + 1][1] = r[3];
            }
#pragma unroll
            for (int nf = 0; nf < 8; nf++)
                mma_f16(of[nf], pa[ks], bf[nf]);
        }
    }

    const float inv0 = 1.0f / l0;
    const float inv1 = 1.0f / l1;
#pragma unroll
    for (int nf = 0; nf < 8; nf++) {
        int col = nf * 8 + 2 * lc;
        *(float2*)(Og + base + (size_t)r0g * DMODEL + col) =
            make_float2(of[nf][0] * inv0, of[nf][1] * inv0);
        *(float2*)(Og + base + (size_t)r1g * DMODEL + col) =
            make_float2(of[nf][2] * inv1, of[nf][3] * inv1);
    }
}

// ---------------------------------------------------------------------------
extern "C" void kernel_launch(void* const* d_in, const int* in_sizes, int n_in,
                              void* d_out, int out_size) {
    const float* x   = (const float*)d_in[0];
    const float* qW1 = (const float*)d_in[1];
    const float* qb1 = (const float*)d_in[2];
    const float* qW2 = (const float*)d_in[3];
    const float* qb2 = (const float*)d_in[4];
    const float* kW1 = (const float*)d_in[5];
    const float* kb1 = (const float*)d_in[6];
    const float* kW2 = (const float*)d_in[7];
    const float* kb2 = (const float*)d_in[8];
    const float* vW1 = (const float*)d_in[9];
    const float* vb1 = (const float*)d_in[10];
    const float* vW2 = (const float*)d_in[11];
    const float* vb2 = (const float*)d_in[12];

    float* out = (float*)d_out;
    const size_t seg = (size_t)MROWS * DMODEL;
    float* k_out = out;
    float* v_out = out + seg;
    float* o_out = out + 2 * seg;

    __half *ghh, *gxh, *gw1t, *gw2t, *gqh, *gkh, *gvh;
    cudaGetSymbolAddress((void**)&ghh, g_hh);
    cudaGetSymbolAddress((void**)&gxh, g_xh);
    cudaGetSymbolAddress((void**)&gw1t, g_w1t);
    cudaGetSymbolAddress((void**)&gw2t, g_w2t);
    cudaGetSymbolAddress((void**)&gqh, g_qh);
    cudaGetSymbolAddress((void**)&gkh, g_kh);
    cudaGetSymbolAddress((void**)&gvh, g_vh);
    __half* gh0 = ghh;
    __half* gh1 = ghh + (size_t)MROWS * HID;
    __half* gh2 = ghh + 2 * (size_t)MROWS * HID;
    __half* w1t0 = gw1t;
    __half* w1t1 = gw1t + (size_t)HID * DMODEL;
    __half* w1t2 = gw1t + 2 * (size_t)HID * DMODEL;
    __half* w2t0 = gw2t;
    __half* w2t1 = gw2t + (size_t)DMODEL * HID;
    __half* w2t2 = gw2t + 2 * (size_t)DMODEL * HID;

    cudaFuncSetAttribute(gemm_mma, cudaFuncAttributeMaxDynamicSharedMemorySize, SM_BYTES);
    cudaFuncSetAttribute(attention_h, cudaFuncAttributeMaxDynamicSharedMemorySize, ATTH_BYTES);

    // Prepass
    {
        int n4 = (MROWS * DMODEL) / 4;
        cvt_x_kernel<<<(n4 + 255) / 256, 256>>>(x, gxh, n4);
        dim3 tb(32, 8);
        transpose_h<<<dim3(HID / 32, DMODEL / 32, 3), tb>>>(qW1, kW1, vW1, w1t0, w1t1, w1t2, DMODEL, HID);
        transpose_h<<<dim3(DMODEL / 32, HID / 32, 3), tb>>>(qW2, kW2, vW2, w2t0, w2t1, w2t2, HID, DMODEL);
    }

    // Stage 1: hidden[z] = fp16(gelu(x @ W1[z] + b1[z]))  — mode 5 (gelu|fp16)
    {
        dim3 g(HID / BN, MROWS / BM, 3);
        gemm_mma<<<g, 256, SM_BYTES>>>(gxh, gxh, gxh,
                                       w1t0, w1t1, w1t2,
                                       qb1, kb1, vb1,
                                       nullptr, nullptr, nullptr,
                                       gh0, gh1, gh2,
                                       HID, DMODEL, (5) | (5 << 4) | (5 << 8));
    }
    // Stage 2: q: fp16*0.125 (mode 12); k: fp32+fp16 (mode 6); v: gelu fp32+fp16 (mode 7)
    {
        dim3 g(DMODEL / BN, MROWS / BM, 3);
        gemm_mma<<<g, 256, SM_BYTES>>>(gh0, gh1, gh2,
                                       w2t0, w2t1, w2t2,
                                       qb2, kb2, vb2,
                                       nullptr, k_out, v_out,
                                       gqh, gkh, gvh,
                                       DMODEL, HID, (12) | (6 << 4) | (7 << 8));
    }
    // Stage 3: attention (fp16 tensor cores, register-resident P)
    {
        dim3 ga(SEQ / 128, 2 * NHEADS);
        attention_h<<<ga, 256, ATTH_BYTES>>>(gqh, gkh, gvh, o_out);
    }
}